// round 11
// baseline (speedup 1.0000x reference)
#include <cuda_runtime.h>
#include <cuda_bf16.h>
#include <cstdint>
#include <cmath>

// Problem constants
#define BATCH   2
#define LSEQ    2048
#define DMODEL  1024
#define DINNER  2048
#define DSTATE  16
#define NROWS   (BATCH*LSEQ)          // 4096
#define XZW     (2*DINNER)            // 4096

// ---------------- scratch (static device arrays; no allocation) ------------
__device__ float g_xz   [(size_t)NROWS * XZW];     // x@W_in (x_|z)
__device__ float g_Bc   [(size_t)NROWS * DSTATE];
__device__ float g_Cc   [(size_t)NROWS * DSTATE];
__device__ float g_delta[NROWS];

// bf16 split operands for tensor-core GEMMs (aligned for 16B cp.async)
__device__ __align__(128) __nv_bfloat16 g_xa_h[(size_t)NROWS * DMODEL];
__device__ __align__(128) __nv_bfloat16 g_xa_l[(size_t)NROWS * DMODEL];
__device__ __align__(128) __nv_bfloat16 g_w1_h[(size_t)XZW * DMODEL];     // W_in^T  [4096,1024]
__device__ __align__(128) __nv_bfloat16 g_w1_l[(size_t)XZW * DMODEL];
__device__ __align__(128) __nv_bfloat16 g_ya_h[(size_t)NROWS * DINNER];
__device__ __align__(128) __nv_bfloat16 g_ya_l[(size_t)NROWS * DINNER];
__device__ __align__(128) __nv_bfloat16 g_w2_h[(size_t)DMODEL * DINNER];  // W_out^T [1024,2048]
__device__ __align__(128) __nv_bfloat16 g_w2_l[(size_t)DMODEL * DINNER];

// ============================ PTX helpers (sm_100-safe) =====================
__device__ __forceinline__ uint32_t smem_u32(const void* p) {
    uint32_t a;
    asm("{ .reg .u64 t; cvta.to.shared.u64 t, %1; cvt.u32.u64 %0, t; }" : "=r"(a) : "l"(p));
    return a;
}
__device__ __forceinline__ void cp16(uint32_t dst, const void* src) {
    asm volatile("cp.async.cg.shared.global [%0], [%1], 16;" :: "r"(dst), "l"(src));
}
__device__ __forceinline__ void cp_commit() {
    asm volatile("cp.async.commit_group;" ::: "memory");
}
__device__ __forceinline__ void ldsm4(uint32_t* r, uint32_t a) {
    asm volatile("ldmatrix.sync.aligned.m8n8.x4.shared.b16 {%0,%1,%2,%3}, [%4];"
        : "=r"(r[0]), "=r"(r[1]), "=r"(r[2]), "=r"(r[3]) : "r"(a));
}
__device__ __forceinline__ void mma16816(float* d, const uint32_t* a, uint32_t b0, uint32_t b1) {
    asm volatile("mma.sync.aligned.m16n8k16.row.col.f32.bf16.bf16.f32 "
        "{%0,%1,%2,%3},{%4,%5,%6,%7},{%8,%9},{%0,%1,%2,%3};"
        : "+f"(d[0]), "+f"(d[1]), "+f"(d[2]), "+f"(d[3])
        : "r"(a[0]), "r"(a[1]), "r"(a[2]), "r"(a[3]), "r"(b0), "r"(b1));
}
__device__ __forceinline__ float silu_f(float v) {
    return v / (1.f + __expf(-v));
}

// ============================================================================
// Tensor-core GEMM:  C = A @ B^T.  CTA 128x128, K chunks of 64, 3-stage
// cp.async pipeline, 512 threads, warp tile 32x32.  NEW: register
// double-buffered fragments — ks+1 LDSMs issued during ks HMMAs.
// ============================================================================
#define STAGE_BYTES 65536u

__global__ __launch_bounds__(512) void gemm_mma(
    const __nv_bfloat16* __restrict__ Ah, const __nv_bfloat16* __restrict__ Al,
    const __nv_bfloat16* __restrict__ Bh, const __nv_bfloat16* __restrict__ Bl,
    float* __restrict__ C, int M, int N, int K)
{
    extern __shared__ char smem[];
    const uint32_t sb = smem_u32(smem);

    const int tid  = threadIdx.x;
    const int lane = tid & 31, wid = tid >> 5;
    const int wm   = wid >> 2, wn = wid & 3;
    const int m0   = blockIdx.y * 128, n0 = blockIdx.x * 128;
    const int NC   = K >> 6;

    const int lrow0 = tid >> 3;
    const int lseg  = tid & 7;
    const int lr    = lane & 15;
    const int lc    = lane >> 4;

    float acc[2][4][4];
#pragma unroll
    for (int i = 0; i < 2; ++i)
#pragma unroll
        for (int j = 0; j < 4; ++j)
#pragma unroll
            for (int q = 0; q < 4; ++q) acc[i][j][q] = 0.f;

    auto LOAD = [&](int c) {
        const int kc = c << 6;
        const uint32_t base = sb + (uint32_t)(c % 3) * STAGE_BYTES;
#pragma unroll
        for (int i = 0; i < 2; ++i) {
            int row = lrow0 + i * 64;
            uint32_t sw = (uint32_t)((lseg ^ (row & 7)) << 4);
            uint32_t ro = (uint32_t)row * 128u + sw;
            cp16(base + ro,          Ah + (size_t)(m0 + row) * K + kc + lseg * 8);
            cp16(base + 16384u + ro, Al + (size_t)(m0 + row) * K + kc + lseg * 8);
            cp16(base + 32768u + ro, Bh + (size_t)(n0 + row) * K + kc + lseg * 8);
            cp16(base + 49152u + ro, Bl + (size_t)(n0 + row) * K + kc + lseg * 8);
        }
        cp_commit();
    };

    LOAD(0);
    if (NC > 1) LOAD(1);

    uint32_t ah[2][2][4], al[2][2][4], bh[2][2][4], bl[2][2][4];  // [buf][..][4]

    for (int c = 0; c < NC; ++c) {
        if (c + 1 < NC) asm volatile("cp.async.wait_group 1;" ::: "memory");
        else            asm volatile("cp.async.wait_group 0;" ::: "memory");
        __syncthreads();
        if (c + 2 < NC) LOAD(c + 2);

        const uint32_t ab = sb + (uint32_t)(c % 3) * STAGE_BYTES;
        const uint32_t bb = ab + 32768u;

        auto LDFRAG = [&](int ks, int buf) {
#pragma unroll
            for (int am = 0; am < 2; ++am) {
                int row = wm * 32 + am * 16 + lr;
                uint32_t c16 = (uint32_t)((ks * 2 + lc) ^ (row & 7));
                uint32_t off = (uint32_t)row * 128u + (c16 << 4);
                ldsm4(ah[buf][am], ab + off);
                ldsm4(al[buf][am], ab + 16384u + off);
            }
#pragma unroll
            for (int nb = 0; nb < 2; ++nb) {
                int row = wn * 32 + nb * 16 + lr;
                uint32_t c16 = (uint32_t)((ks * 2 + lc) ^ (row & 7));
                uint32_t off = (uint32_t)row * 128u + (c16 << 4);
                ldsm4(bh[buf][nb], bb + off);
                ldsm4(bl[buf][nb], bb + 16384u + off);
            }
        };

        LDFRAG(0, 0);
#pragma unroll
        for (int ks = 0; ks < 4; ++ks) {
            const int cur = ks & 1;
            if (ks < 3) LDFRAG(ks + 1, cur ^ 1);   // prefetch next fragments
            // term-major HMMAs on current buffer
#pragma unroll
            for (int am = 0; am < 2; ++am)
#pragma unroll
                for (int nb = 0; nb < 2; ++nb)
#pragma unroll
                    for (int h2 = 0; h2 < 2; ++h2)
                        mma16816(acc[am][nb * 2 + h2], ah[cur][am], bh[cur][nb][h2], bh[cur][nb][h2 + 2]);
#pragma unroll
            for (int am = 0; am < 2; ++am)
#pragma unroll
                for (int nb = 0; nb < 2; ++nb)
#pragma unroll
                    for (int h2 = 0; h2 < 2; ++h2)
                        mma16816(acc[am][nb * 2 + h2], ah[cur][am], bl[cur][nb][h2], bl[cur][nb][h2 + 2]);
#pragma unroll
            for (int am = 0; am < 2; ++am)
#pragma unroll
                for (int nb = 0; nb < 2; ++nb)
#pragma unroll
                    for (int h2 = 0; h2 < 2; ++h2)
                        mma16816(acc[am][nb * 2 + h2], al[cur][am], bh[cur][nb][h2], bh[cur][nb][h2 + 2]);
        }
    }

    const int er = lane >> 2, ec = (lane & 3) * 2;
#pragma unroll
    for (int am = 0; am < 2; ++am) {
        int row = m0 + wm * 32 + am * 16 + er;
#pragma unroll
        for (int na = 0; na < 4; ++na) {
            int col = n0 + wn * 32 + na * 8 + ec;
            float* d = acc[am][na];
            *reinterpret_cast<float2*>(C + (size_t)row * N + col)       = make_float2(d[0], d[1]);
            *reinterpret_cast<float2*>(C + (size_t)(row + 8) * N + col) = make_float2(d[2], d[3]);
        }
    }
}

// ============================================================================
// fp32 -> (hi,lo) bf16 split, elementwise (x4 vectorized)
// ============================================================================
__global__ __launch_bounds__(256) void split_bf16_k(
    const float* __restrict__ in, __nv_bfloat16* __restrict__ hi,
    __nv_bfloat16* __restrict__ lo, int n4)
{
    int i = blockIdx.x * 256 + threadIdx.x;
    if (i >= n4) return;
    float4 v = reinterpret_cast<const float4*>(in)[i];
    __nv_bfloat16 h0 = __float2bfloat16(v.x), h1 = __float2bfloat16(v.y);
    __nv_bfloat16 h2 = __float2bfloat16(v.z), h3 = __float2bfloat16(v.w);
    reinterpret_cast<__nv_bfloat162*>(hi)[2 * i]     = __halves2bfloat162(h0, h1);
    reinterpret_cast<__nv_bfloat162*>(hi)[2 * i + 1] = __halves2bfloat162(h2, h3);
    __nv_bfloat16 l0 = __float2bfloat16(v.x - __bfloat162float(h0));
    __nv_bfloat16 l1 = __float2bfloat16(v.y - __bfloat162float(h1));
    __nv_bfloat16 l2 = __float2bfloat16(v.z - __bfloat162float(h2));
    __nv_bfloat16 l3 = __float2bfloat16(v.w - __bfloat162float(h3));
    reinterpret_cast<__nv_bfloat162*>(lo)[2 * i]     = __halves2bfloat162(l0, l1);
    reinterpret_cast<__nv_bfloat162*>(lo)[2 * i + 1] = __halves2bfloat162(l2, l3);
}

// ============================================================================
// W[K,N] fp32 -> Wt hi/lo [N,K] bf16 (transpose + split)
// ============================================================================
__global__ __launch_bounds__(256) void tr_split_k(
    const float* __restrict__ W, __nv_bfloat16* __restrict__ hi,
    __nv_bfloat16* __restrict__ lo, int K, int N)
{
    __shared__ float t[32][33];
    const int k0 = blockIdx.y * 32, n0 = blockIdx.x * 32;
    const int tx = threadIdx.x & 31, ty = threadIdx.x >> 5;
#pragma unroll
    for (int i = 0; i < 4; ++i)
        t[ty + i * 8][tx] = W[(size_t)(k0 + ty + i * 8) * N + n0 + tx];
    __syncthreads();
#pragma unroll
    for (int i = 0; i < 4; ++i) {
        int n = n0 + ty + i * 8;
        float v = t[tx][ty + i * 8];
        __nv_bfloat16 h = __float2bfloat16(v);
        hi[(size_t)n * K + k0 + tx] = h;
        lo[(size_t)n * K + k0 + tx] = __float2bfloat16(v - __bfloat162float(h));
    }
}

// ============================================================================
// bcd = silu(conv(x_)) @ W_x  (conv+SiLU fused into staging; g_xs eliminated)
// ============================================================================
__global__ __launch_bounds__(256) void bcd_k(
    const float* __restrict__ xz, const float* __restrict__ cw,
    const float* __restrict__ cb, const float* __restrict__ Wx,
    float* __restrict__ gB, float* __restrict__ gC, float* __restrict__ gdelta)
{
    __shared__ float sX[32 * 33];
    __shared__ float sW[32 * 36];

    const int tid  = threadIdx.x;
    const int row0 = blockIdx.x * 32;
    const int row  = tid & 31;
    const int g    = tid >> 5;

    // staging mapping: thread -> (row r, 4 channels within chunk)
    const int r   = tid >> 3;
    const int c4g = (tid & 7) << 2;
    const size_t grow_s = (size_t)(row0 + r);
    const int l_s = (int)(grow_s & (LSEQ - 1));

    float acc0 = 0.f, acc1 = 0.f, acc2 = 0.f, acc3 = 0.f, accd = 0.f;

    for (int kc = 0; kc < DINNER; kc += 32) {
        for (int e = tid; e < 32 * 36; e += 256) {
            int k = e / 36, n = e - k * 36;
            sW[e] = (n < 33) ? Wx[(size_t)(kc + k) * 33 + n] : 0.f;
        }
        {
            const int dch = kc + c4g;
            float4 bias = *reinterpret_cast<const float4*>(cb + dch);
            float4 w0 = reinterpret_cast<const float4*>(cw)[dch + 0];
            float4 w1 = reinterpret_cast<const float4*>(cw)[dch + 1];
            float4 w2 = reinterpret_cast<const float4*>(cw)[dch + 2];
            float4 w3 = reinterpret_cast<const float4*>(cw)[dch + 3];
            float4 t[4];
#pragma unroll
            for (int j = 0; j < 4; ++j) {
                int ll = l_s - 3 + j;
                t[j] = (ll >= 0)
                     ? *reinterpret_cast<const float4*>(xz + (grow_s - 3 + j) * XZW + dch)
                     : make_float4(0.f, 0.f, 0.f, 0.f);
            }
            float4 v = bias;
#pragma unroll
            for (int j = 0; j < 4; ++j) {
                v.x = fmaf((&w0.x)[j], t[j].x, v.x);
                v.y = fmaf((&w1.x)[j], t[j].y, v.y);
                v.z = fmaf((&w2.x)[j], t[j].z, v.z);
                v.w = fmaf((&w3.x)[j], t[j].w, v.w);
            }
            v.x = silu_f(v.x); v.y = silu_f(v.y); v.z = silu_f(v.z); v.w = silu_f(v.w);
            sX[(c4g + 0) * 33 + r] = v.x;
            sX[(c4g + 1) * 33 + r] = v.y;
            sX[(c4g + 2) * 33 + r] = v.z;
            sX[(c4g + 3) * 33 + r] = v.w;
        }
        __syncthreads();
#pragma unroll 8
        for (int k = 0; k < 32; ++k) {
            float  xv = sX[k * 33 + row];
            float4 wv = *(const float4*)(&sW[k * 36 + g * 4]);
            acc0 = fmaf(xv, wv.x, acc0);
            acc1 = fmaf(xv, wv.y, acc1);
            acc2 = fmaf(xv, wv.z, acc2);
            acc3 = fmaf(xv, wv.w, acc3);
            if (g == 0) accd = fmaf(xv, sW[k * 36 + 32], accd);
        }
        __syncthreads();
    }

    const int grow = row0 + row;
    float a[4] = {acc0, acc1, acc2, acc3};
#pragma unroll
    for (int j = 0; j < 4; ++j) {
        int nn = g * 4 + j;
        if (nn < 16) gB[(size_t)grow * 16 + nn]        = a[j];
        else         gC[(size_t)grow * 16 + (nn - 16)] = a[j];
    }
    if (g == 0) gdelta[grow] = accd;
}

// ============================================================================
// Selective scan: conv+SiLU fused into staging (reads xz directly; g_xs gone),
// fused softplus, skip, gate, bf16 hi/lo split output.
// smem (floats): sB 1024 | sC 1024 | sdx 2048 | sz 1024 | sp 20480 | sDp 16
// ============================================================================
#define SCAN_SMEM_FLOATS (25600 + 16)

__global__ __launch_bounds__(256) void scan_k(
    const float* __restrict__ gdelta, const float* __restrict__ w_dt,
    const float* __restrict__ b_dt,
    const float* __restrict__ xz,
    const float* __restrict__ cw,   const float* __restrict__ cb,
    const float* __restrict__ gB,   const float* __restrict__ gC,
    const float* __restrict__ A_log, const float* __restrict__ Dp,
    __nv_bfloat16* __restrict__ yh, __nv_bfloat16* __restrict__ yl)
{
    extern __shared__ float sm[];
    float*  sB  = sm;
    float*  sC  = sm + 1024;
    float2* sdx = (float2*)(sm + 2048);
    float*  sz  = sm + 4096;
    float*  sp  = sm + 5120;
    float*  sDp = sm + 25600;

    const int tid  = threadIdx.x;
    const int lane = tid & 31;
    const int w    = tid >> 5;
    const int cidx = 2 * w + (lane >> 4);
    const int n    = lane & 15;
    const int b    = blockIdx.x >> 7;
    const int d0   = (blockIdx.x & 127) * 16;
    const int d    = d0 + cidx;

    if (tid < 16) sDp[tid] = Dp[d0 + tid];

    const float A = -expf(A_log[d * DSTATE + n]);
    float h = 0.f;
    const int spb = cidx * 20 + n;

    // staging/epilogue mapping: thread -> (row sl, 4 channels c0)
    const int sl = tid >> 2;
    const int c0 = (tid & 3) << 2;
    const float4 wd = *reinterpret_cast<const float4*>(w_dt + d0 + c0);
    const float4 bd = *reinterpret_cast<const float4*>(b_dt + d0 + c0);
    const float4 bias = *reinterpret_cast<const float4*>(cb + d0 + c0);
    const float4 w0 = reinterpret_cast<const float4*>(cw)[d0 + c0 + 0];
    const float4 w1 = reinterpret_cast<const float4*>(cw)[d0 + c0 + 1];
    const float4 w2 = reinterpret_cast<const float4*>(cw)[d0 + c0 + 2];
    const float4 w3 = reinterpret_cast<const float4*>(cw)[d0 + c0 + 3];

    for (int t0 = 0; t0 < LSEQ; t0 += 64) {
        // ---- stage tiles: conv+silu from xz, softplus dt, z ----
        {
            size_t base_bc = (size_t)(b * LSEQ + t0) * DSTATE;
            ((float4*)sB)[tid] = ((const float4*)(gB + base_bc))[tid];
            ((float4*)sC)[tid] = ((const float4*)(gC + base_bc))[tid];

            const int l = t0 + sl;
            size_t grow = (size_t)(b * LSEQ + l);
            float4 t[4];
#pragma unroll
            for (int j = 0; j < 4; ++j) {
                int ll = l - 3 + j;
                t[j] = (ll >= 0)
                     ? *reinterpret_cast<const float4*>(xz + (grow - 3 + j) * XZW + d0 + c0)
                     : make_float4(0.f, 0.f, 0.f, 0.f);
            }
            float4 xv = bias;
#pragma unroll
            for (int j = 0; j < 4; ++j) {
                xv.x = fmaf((&w0.x)[j], t[j].x, xv.x);
                xv.y = fmaf((&w1.x)[j], t[j].y, xv.y);
                xv.z = fmaf((&w2.x)[j], t[j].z, xv.z);
                xv.w = fmaf((&w3.x)[j], t[j].w, xv.w);
            }
            xv.x = silu_f(xv.x); xv.y = silu_f(xv.y);
            xv.z = silu_f(xv.z); xv.w = silu_f(xv.w);

            float4 zv = *reinterpret_cast<const float4*>(xz + grow * XZW + DINNER + d0 + c0);
            float  del = gdelta[grow];

            float sp0 = fmaf(del, wd.x, bd.x);
            float sp1 = fmaf(del, wd.y, bd.y);
            float sp2 = fmaf(del, wd.z, bd.z);
            float sp3 = fmaf(del, wd.w, bd.w);
            sp0 = (sp0 > 30.f) ? sp0 : log1pf(__expf(sp0));
            sp1 = (sp1 > 30.f) ? sp1 : log1pf(__expf(sp1));
            sp2 = (sp2 > 30.f) ? sp2 : log1pf(__expf(sp2));
            sp3 = (sp3 > 30.f) ? sp3 : log1pf(__expf(sp3));

            float2* dsx = sdx + sl * 16 + c0;
            dsx[0] = make_float2(sp0, xv.x);
            dsx[1] = make_float2(sp1, xv.y);
            dsx[2] = make_float2(sp2, xv.z);
            dsx[3] = make_float2(sp3, xv.w);
            *reinterpret_cast<float4*>(sz + sl * 16 + c0) = zv;
        }
        __syncthreads();

        // ---- 64 sequential steps: recurrence only, partials to smem ----
#pragma unroll 4
        for (int l = 0; l < 64; ++l) {
            float2 dx = sdx[l * 16 + cidx];
            float  Bv = sB [l * 16 + n];
            float  Cv = sC [l * 16 + n];
            float  a  = __expf(dx.x * A);
            h = fmaf(a, h, dx.x * dx.y * Bv);
            sp[l * 320 + spb] = h * Cv;
        }
        __syncthreads();

        // ---- epilogue: 4 channels per thread, packed bf16x2 stores ----
        {
            size_t grow = (size_t)(b * LSEQ + t0 + sl);
            float gv[4];
#pragma unroll
            for (int j = 0; j < 4; ++j) {
                int ch = c0 + j;
                const float4* row4 = (const float4*)(sp + sl * 320 + ch * 20);
                float4 r0 = row4[0], r1 = row4[1], r2 = row4[2], r3 = row4[3];
                float s = ((r0.x + r0.y) + (r0.z + r0.w)) + ((r1.x + r1.y) + (r1.z + r1.w))
                        + ((r2.x + r2.y) + (r2.z + r2.w)) + ((r3.x + r3.y) + (r3.z + r3.w));
                float xv = sdx[sl * 16 + ch].y;
                float y  = fmaf(xv, sDp[ch], s);
                float zv = sz[sl * 16 + ch];
                gv[j] = y * silu_f(zv);
            }
            __nv_bfloat16 h0 = __float2bfloat16(gv[0]), h1 = __float2bfloat16(gv[1]);
            __nv_bfloat16 h2 = __float2bfloat16(gv[2]), h3 = __float2bfloat16(gv[3]);
            __nv_bfloat162 ph0 = __halves2bfloat162(h0, h1);
            __nv_bfloat162 ph1 = __halves2bfloat162(h2, h3);
            __nv_bfloat162 pl0 = __halves2bfloat162(
                __float2bfloat16(gv[0] - __bfloat162float(h0)),
                __float2bfloat16(gv[1] - __bfloat162float(h1)));
            __nv_bfloat162 pl1 = __halves2bfloat162(
                __float2bfloat16(gv[2] - __bfloat162float(h2)),
                __float2bfloat16(gv[3] - __bfloat162float(h3)));
            __nv_bfloat162* ph = reinterpret_cast<__nv_bfloat162*>(yh + grow * DINNER + d0 + c0);
            __nv_bfloat162* pl = reinterpret_cast<__nv_bfloat162*>(yl + grow * DINNER + d0 + c0);
            ph[0] = ph0; ph[1] = ph1;
            pl[0] = pl0; pl[1] = pl1;
        }
        __syncthreads();
    }
}

// ============================================================================
// launch
// ============================================================================
extern "C" void kernel_launch(void* const* d_in, const int* in_sizes, int n_in,
                              void* d_out, int out_size)
{
    const float* x     = (const float*)d_in[0];
    const float* W_in  = (const float*)d_in[1];
    const float* convw = (const float*)d_in[2];
    const float* convb = (const float*)d_in[3];
    const float* W_x   = (const float*)d_in[4];
    const float* w_dt  = (const float*)d_in[5];
    const float* b_dt  = (const float*)d_in[6];
    const float* A_log = (const float*)d_in[7];
    const float* Dp    = (const float*)d_in[8];
    const float* W_out = (const float*)d_in[9];
    float* out = (float*)d_out;

    float *p_xz, *p_B, *p_C, *p_delta;
    cudaGetSymbolAddress((void**)&p_xz,    g_xz);
    cudaGetSymbolAddress((void**)&p_B,     g_Bc);
    cudaGetSymbolAddress((void**)&p_C,     g_Cc);
    cudaGetSymbolAddress((void**)&p_delta, g_delta);

    __nv_bfloat16 *xa_h, *xa_l, *w1_h, *w1_l, *ya_h, *ya_l, *w2_h, *w2_l;
    cudaGetSymbolAddress((void**)&xa_h, g_xa_h);
    cudaGetSymbolAddress((void**)&xa_l, g_xa_l);
    cudaGetSymbolAddress((void**)&w1_h, g_w1_h);
    cudaGetSymbolAddress((void**)&w1_l, g_w1_l);
    cudaGetSymbolAddress((void**)&ya_h, g_ya_h);
    cudaGetSymbolAddress((void**)&ya_l, g_ya_l);
    cudaGetSymbolAddress((void**)&w2_h, g_w2_h);
    cudaGetSymbolAddress((void**)&w2_l, g_w2_l);

    constexpr int GSMEM = 3 * 65536;
    constexpr int SSMEM = SCAN_SMEM_FLOATS * 4;
    cudaFuncSetAttribute((const void*)gemm_mma,
                         cudaFuncAttributeMaxDynamicSharedMemorySize, GSMEM);
    cudaFuncSetAttribute((const void*)scan_k,
                         cudaFuncAttributeMaxDynamicSharedMemorySize, SSMEM);

    // prep: weight transpose+split, x split
    tr_split_k<<<dim3(XZW / 32, DMODEL / 32), 256>>>(W_in, w1_h, w1_l, DMODEL, XZW);
    tr_split_k<<<dim3(DMODEL / 32, DINNER / 32), 256>>>(W_out, w2_h, w2_l, DINNER, DMODEL);
    split_bf16_k<<<(NROWS * DMODEL / 4 + 255) / 256, 256>>>(x, xa_h, xa_l, NROWS * DMODEL / 4);

    // 1. xz = x @ W_in
    gemm_mma<<<dim3(XZW / 128, NROWS / 128), 512, GSMEM>>>(
        xa_h, xa_l, w1_h, w1_l, p_xz, NROWS, XZW, DMODEL);

    // 2. B, C, delta  (conv+silu fused into staging)
    bcd_k<<<NROWS / 32, 256>>>(p_xz, convw, convb, W_x, p_B, p_C, p_delta);

    // 3. selective scan (conv+silu, softplus, skip, gate, bf16 split fused)
    scan_k<<<BATCH * (DINNER / 16), 256, SSMEM>>>(
        p_delta, w_dt, b_dt, p_xz, convw, convb, p_B, p_C, A_log, Dp, ya_h, ya_l);

    // 4. out = yz @ W_out
    gemm_mma<<<dim3(DMODEL / 128, NROWS / 128), 512, GSMEM>>>(
        ya_h, ya_l, w2_h, w2_l, out, NROWS, DMODEL, DINNER);
}

// round 12
// speedup vs baseline: 1.0471x; 1.0471x over previous
#include <cuda_runtime.h>
#include <cuda_bf16.h>
#include <cstdint>
#include <cmath>

// Problem constants
#define BATCH   2
#define LSEQ    2048
#define DMODEL  1024
#define DINNER  2048
#define DSTATE  16
#define NROWS   (BATCH*LSEQ)          // 4096
#define XZW     (2*DINNER)            // 4096

// ---------------- scratch (static device arrays; no allocation) ------------
__device__ float g_xz   [(size_t)NROWS * XZW];     // x@W_in (x_|z)
__device__ float g_xs   [(size_t)NROWS * DINNER];  // silu(conv(x_))
__device__ float g_Bc   [(size_t)NROWS * DSTATE];
__device__ float g_Cc   [(size_t)NROWS * DSTATE];
__device__ float g_delta[NROWS];

// bf16 split operands for tensor-core GEMMs (aligned for 16B cp.async)
__device__ __align__(128) __nv_bfloat16 g_xa_h[(size_t)NROWS * DMODEL];
__device__ __align__(128) __nv_bfloat16 g_xa_l[(size_t)NROWS * DMODEL];
__device__ __align__(128) __nv_bfloat16 g_w1_h[(size_t)XZW * DMODEL];     // W_in^T  [4096,1024]
__device__ __align__(128) __nv_bfloat16 g_w1_l[(size_t)XZW * DMODEL];
__device__ __align__(128) __nv_bfloat16 g_ya_h[(size_t)NROWS * DINNER];
__device__ __align__(128) __nv_bfloat16 g_ya_l[(size_t)NROWS * DINNER];
__device__ __align__(128) __nv_bfloat16 g_w2_h[(size_t)DMODEL * DINNER];  // W_out^T [1024,2048]
__device__ __align__(128) __nv_bfloat16 g_w2_l[(size_t)DMODEL * DINNER];

// ============================ PTX helpers (sm_100-safe) =====================
__device__ __forceinline__ uint32_t smem_u32(const void* p) {
    uint32_t a;
    asm("{ .reg .u64 t; cvta.to.shared.u64 t, %1; cvt.u32.u64 %0, t; }" : "=r"(a) : "l"(p));
    return a;
}
__device__ __forceinline__ void cp16(uint32_t dst, const void* src) {
    asm volatile("cp.async.cg.shared.global [%0], [%1], 16;" :: "r"(dst), "l"(src));
}
__device__ __forceinline__ void cp_commit() {
    asm volatile("cp.async.commit_group;" ::: "memory");
}
__device__ __forceinline__ void ldsm4(uint32_t* r, uint32_t a) {
    asm volatile("ldmatrix.sync.aligned.m8n8.x4.shared.b16 {%0,%1,%2,%3}, [%4];"
        : "=r"(r[0]), "=r"(r[1]), "=r"(r[2]), "=r"(r[3]) : "r"(a));
}
__device__ __forceinline__ void mma16816(float* d, const uint32_t* a, uint32_t b0, uint32_t b1) {
    asm volatile("mma.sync.aligned.m16n8k16.row.col.f32.bf16.bf16.f32 "
        "{%0,%1,%2,%3},{%4,%5,%6,%7},{%8,%9},{%0,%1,%2,%3};"
        : "+f"(d[0]), "+f"(d[1]), "+f"(d[2]), "+f"(d[3])
        : "r"(a[0]), "r"(a[1]), "r"(a[2]), "r"(a[3]), "r"(b0), "r"(b1));
}
__device__ __forceinline__ float silu_f(float v) {
    return v / (1.f + __expf(-v));
}

// ============================================================================
// Tensor-core GEMM:  C = A @ B^T.  NEW GEOMETRY: CTA tile 128x64, K chunks
// of 64, 2-stage cp.async pipeline, stage 48KB -> 96KB/CTA -> 2 CTAs/SM.
// 256 threads (8 warps, 4m x 2n, warp tile 32x32).  Cross-CTA overlap hides
// barrier/ldsm bubbles that intra-CTA scheduling could not.
// ============================================================================
#define STAGE_BYTES 49152u   // Ah 16K | Al 16K | Bh 8K | Bl 8K

__global__ __launch_bounds__(256, 2) void gemm_mma(
    const __nv_bfloat16* __restrict__ Ah, const __nv_bfloat16* __restrict__ Al,
    const __nv_bfloat16* __restrict__ Bh, const __nv_bfloat16* __restrict__ Bl,
    float* __restrict__ C, int M, int N, int K)
{
    extern __shared__ char smem[];
    const uint32_t sb = smem_u32(smem);

    const int tid  = threadIdx.x;
    const int lane = tid & 31, wid = tid >> 5;      // 8 warps
    const int wm   = wid >> 1, wn = wid & 1;        // 4m x 2n
    const int m0   = blockIdx.y * 128, n0 = blockIdx.x * 64;
    const int NC   = K >> 6;

    const int lrow0 = tid >> 3;   // 0..31 (loader)
    const int lseg  = tid & 7;
    const int lr    = lane & 15;
    const int lc    = lane >> 4;

    float acc[2][4][4];
#pragma unroll
    for (int i = 0; i < 2; ++i)
#pragma unroll
        for (int j = 0; j < 4; ++j)
#pragma unroll
            for (int q = 0; q < 4; ++q) acc[i][j][q] = 0.f;

    auto LOAD = [&](int c) {
        const int kc = c << 6;
        const uint32_t base = sb + (uint32_t)(c & 1) * STAGE_BYTES;
        // A: 128 rows, hi+lo
#pragma unroll
        for (int i = 0; i < 4; ++i) {
            int row = lrow0 + i * 32;
            uint32_t ro = (uint32_t)row * 128u + (uint32_t)((lseg ^ (row & 7)) << 4);
            cp16(base + ro,          Ah + (size_t)(m0 + row) * K + kc + lseg * 8);
            cp16(base + 16384u + ro, Al + (size_t)(m0 + row) * K + kc + lseg * 8);
        }
        // B: 64 rows, hi+lo
#pragma unroll
        for (int i = 0; i < 2; ++i) {
            int row = lrow0 + i * 32;
            uint32_t ro = (uint32_t)row * 128u + (uint32_t)((lseg ^ (row & 7)) << 4);
            cp16(base + 32768u + ro, Bh + (size_t)(n0 + row) * K + kc + lseg * 8);
            cp16(base + 40960u + ro, Bl + (size_t)(n0 + row) * K + kc + lseg * 8);
        }
        cp_commit();
    };

    LOAD(0);
    if (NC > 1) LOAD(1);

    for (int c = 0; c < NC; ++c) {
        if (c + 1 < NC) asm volatile("cp.async.wait_group 1;" ::: "memory");
        else            asm volatile("cp.async.wait_group 0;" ::: "memory");
        __syncthreads();

        const uint32_t ab = sb + (uint32_t)(c & 1) * STAGE_BYTES;
        const uint32_t bb = ab + 32768u;

#pragma unroll
        for (int ks = 0; ks < 4; ++ks) {
            uint32_t ah[2][4], al[2][4], bh[2][4], bl[2][4];
#pragma unroll
            for (int am = 0; am < 2; ++am) {
                int row = wm * 32 + am * 16 + lr;
                uint32_t c16 = (uint32_t)((ks * 2 + lc) ^ (row & 7));
                uint32_t off = (uint32_t)row * 128u + (c16 << 4);
                ldsm4(ah[am], ab + off);
                ldsm4(al[am], ab + 16384u + off);
            }
#pragma unroll
            for (int nb = 0; nb < 2; ++nb) {
                int row = wn * 32 + nb * 16 + lr;
                uint32_t c16 = (uint32_t)((ks * 2 + lc) ^ (row & 7));
                uint32_t off = (uint32_t)row * 128u + (c16 << 4);
                ldsm4(bh[nb], bb + off);
                ldsm4(bl[nb], bb + 8192u + off);
            }
            // term-major 3-term split accumulation
#pragma unroll
            for (int am = 0; am < 2; ++am)
#pragma unroll
                for (int nb = 0; nb < 2; ++nb)
#pragma unroll
                    for (int h2 = 0; h2 < 2; ++h2)
                        mma16816(acc[am][nb * 2 + h2], ah[am], bh[nb][h2], bh[nb][h2 + 2]);
#pragma unroll
            for (int am = 0; am < 2; ++am)
#pragma unroll
                for (int nb = 0; nb < 2; ++nb)
#pragma unroll
                    for (int h2 = 0; h2 < 2; ++h2)
                        mma16816(acc[am][nb * 2 + h2], ah[am], bl[nb][h2], bl[nb][h2 + 2]);
#pragma unroll
            for (int am = 0; am < 2; ++am)
#pragma unroll
                for (int nb = 0; nb < 2; ++nb)
#pragma unroll
                    for (int h2 = 0; h2 < 2; ++h2)
                        mma16816(acc[am][nb * 2 + h2], al[am], bh[nb][h2], bh[nb][h2 + 2]);
        }
        __syncthreads();
        if (c + 2 < NC) LOAD(c + 2);
    }

    const int er = lane >> 2, ec = (lane & 3) * 2;
#pragma unroll
    for (int am = 0; am < 2; ++am) {
        int row = m0 + wm * 32 + am * 16 + er;
#pragma unroll
        for (int na = 0; na < 4; ++na) {
            int col = n0 + wn * 32 + na * 8 + ec;
            float* d = acc[am][na];
            *reinterpret_cast<float2*>(C + (size_t)row * N + col)       = make_float2(d[0], d[1]);
            *reinterpret_cast<float2*>(C + (size_t)(row + 8) * N + col) = make_float2(d[2], d[3]);
        }
    }
}

// ============================================================================
// fp32 -> (hi,lo) bf16 split, elementwise (x4 vectorized)
// ============================================================================
__global__ __launch_bounds__(256) void split_bf16_k(
    const float* __restrict__ in, __nv_bfloat16* __restrict__ hi,
    __nv_bfloat16* __restrict__ lo, int n4)
{
    int i = blockIdx.x * 256 + threadIdx.x;
    if (i >= n4) return;
    float4 v = reinterpret_cast<const float4*>(in)[i];
    __nv_bfloat16 h0 = __float2bfloat16(v.x), h1 = __float2bfloat16(v.y);
    __nv_bfloat16 h2 = __float2bfloat16(v.z), h3 = __float2bfloat16(v.w);
    reinterpret_cast<__nv_bfloat162*>(hi)[2 * i]     = __halves2bfloat162(h0, h1);
    reinterpret_cast<__nv_bfloat162*>(hi)[2 * i + 1] = __halves2bfloat162(h2, h3);
    __nv_bfloat16 l0 = __float2bfloat16(v.x - __bfloat162float(h0));
    __nv_bfloat16 l1 = __float2bfloat16(v.y - __bfloat162float(h1));
    __nv_bfloat16 l2 = __float2bfloat16(v.z - __bfloat162float(h2));
    __nv_bfloat16 l3 = __float2bfloat16(v.w - __bfloat162float(h3));
    reinterpret_cast<__nv_bfloat162*>(lo)[2 * i]     = __halves2bfloat162(l0, l1);
    reinterpret_cast<__nv_bfloat162*>(lo)[2 * i + 1] = __halves2bfloat162(l2, l3);
}

// ============================================================================
// W[K,N] fp32 -> Wt hi/lo [N,K] bf16 (transpose + split)
// ============================================================================
__global__ __launch_bounds__(256) void tr_split_k(
    const float* __restrict__ W, __nv_bfloat16* __restrict__ hi,
    __nv_bfloat16* __restrict__ lo, int K, int N)
{
    __shared__ float t[32][33];
    const int k0 = blockIdx.y * 32, n0 = blockIdx.x * 32;
    const int tx = threadIdx.x & 31, ty = threadIdx.x >> 5;
#pragma unroll
    for (int i = 0; i < 4; ++i)
        t[ty + i * 8][tx] = W[(size_t)(k0 + ty + i * 8) * N + n0 + tx];
    __syncthreads();
#pragma unroll
    for (int i = 0; i < 4; ++i) {
        int n = n0 + ty + i * 8;
        float v = t[tx][ty + i * 8];
        __nv_bfloat16 h = __float2bfloat16(v);
        hi[(size_t)n * K + k0 + tx] = h;
        lo[(size_t)n * K + k0 + tx] = __float2bfloat16(v - __bfloat162float(h));
    }
}

// ============================================================================
// Depthwise causal conv (k=4) + bias + SiLU.  4 consecutive l per thread.
// ============================================================================
__global__ __launch_bounds__(256) void conv_silu_k(
    const float* __restrict__ xz, const float* __restrict__ cw,
    const float* __restrict__ cb, float* __restrict__ xs)
{
    int idx  = blockIdx.x * 256 + threadIdx.x;
    int d4   = (idx & (DINNER / 4 - 1)) << 2;
    int rb   = idx >> 9;
    int r0   = rb << 2;
    int l0   = r0 & (LSEQ - 1);

    float4 bias = *reinterpret_cast<const float4*>(cb + d4);
    float4 w0 = reinterpret_cast<const float4*>(cw)[d4 + 0];
    float4 w1 = reinterpret_cast<const float4*>(cw)[d4 + 1];
    float4 w2 = reinterpret_cast<const float4*>(cw)[d4 + 2];
    float4 w3 = reinterpret_cast<const float4*>(cw)[d4 + 3];

    float4 v[7];
#pragma unroll
    for (int j = 0; j < 7; ++j) {
        int l = l0 - 3 + j;
        v[j] = (l >= 0)
             ? *reinterpret_cast<const float4*>(xz + (size_t)(r0 - 3 + j) * XZW + d4)
             : make_float4(0.f, 0.f, 0.f, 0.f);
    }
#pragma unroll
    for (int i = 0; i < 4; ++i) {
        float4 acc = bias;
#pragma unroll
        for (int k = 0; k < 4; ++k) {
            float4 xv = v[i + k];
            acc.x = fmaf((&w0.x)[k], xv.x, acc.x);
            acc.y = fmaf((&w1.x)[k], xv.y, acc.y);
            acc.z = fmaf((&w2.x)[k], xv.z, acc.z);
            acc.w = fmaf((&w3.x)[k], xv.w, acc.w);
        }
        acc.x = silu_f(acc.x); acc.y = silu_f(acc.y);
        acc.z = silu_f(acc.z); acc.w = silu_f(acc.w);
        *reinterpret_cast<float4*>(xs + (size_t)(r0 + i) * DINNER + d4) = acc;
    }
}

// ============================================================================
// bcd = xs @ W_x  (K=2048, N=33) -> B, C, delta
// ============================================================================
__global__ __launch_bounds__(256) void bcd_k(
    const float* __restrict__ xs, const float* __restrict__ Wx,
    float* __restrict__ gB, float* __restrict__ gC, float* __restrict__ gdelta)
{
    __shared__ float sX[32 * 33];
    __shared__ float sW[32 * 36];

    const int tid  = threadIdx.x;
    const int row0 = blockIdx.x * 32;
    const int row  = tid & 31;
    const int g    = tid >> 5;

    float acc0 = 0.f, acc1 = 0.f, acc2 = 0.f, acc3 = 0.f, accd = 0.f;

    for (int kc = 0; kc < DINNER; kc += 32) {
        for (int e = tid; e < 32 * 36; e += 256) {
            int k = e / 36, n = e - k * 36;
            sW[e] = (n < 33) ? Wx[(size_t)(kc + k) * 33 + n] : 0.f;
        }
        {
            int r = tid >> 3, c4 = tid & 7;
            float4 v = *(const float4*)(xs + (size_t)(row0 + r) * DINNER + kc + c4 * 4);
            int kk = c4 * 4;
            sX[(kk + 0) * 33 + r] = v.x;
            sX[(kk + 1) * 33 + r] = v.y;
            sX[(kk + 2) * 33 + r] = v.z;
            sX[(kk + 3) * 33 + r] = v.w;
        }
        __syncthreads();
#pragma unroll 8
        for (int k = 0; k < 32; ++k) {
            float  xv = sX[k * 33 + row];
            float4 wv = *(const float4*)(&sW[k * 36 + g * 4]);
            acc0 = fmaf(xv, wv.x, acc0);
            acc1 = fmaf(xv, wv.y, acc1);
            acc2 = fmaf(xv, wv.z, acc2);
            acc3 = fmaf(xv, wv.w, acc3);
            if (g == 0) accd = fmaf(xv, sW[k * 36 + 32], accd);
        }
        __syncthreads();
    }

    const int grow = row0 + row;
    float a[4] = {acc0, acc1, acc2, acc3};
#pragma unroll
    for (int j = 0; j < 4; ++j) {
        int nn = g * 4 + j;
        if (nn < 16) gB[(size_t)grow * 16 + nn]        = a[j];
        else         gC[(size_t)grow * 16 + (nn - 16)] = a[j];
    }
    if (g == 0) gdelta[grow] = accd;
}

// ============================================================================
// Selective scan v3 (R10 measured config): vectorized staging, smem-partial
// serial loop, vectorized epilogue with packed bf16x2 stores.
// ============================================================================
#define SCAN_SMEM_FLOATS (25600 + 16)

__global__ __launch_bounds__(256) void scan_k(
    const float* __restrict__ gdelta, const float* __restrict__ w_dt,
    const float* __restrict__ b_dt,
    const float* __restrict__ gxs,  const float* __restrict__ gxz,
    const float* __restrict__ gB,   const float* __restrict__ gC,
    const float* __restrict__ A_log, const float* __restrict__ Dp,
    __nv_bfloat16* __restrict__ yh, __nv_bfloat16* __restrict__ yl)
{
    extern __shared__ float sm[];
    float*  sB  = sm;
    float*  sC  = sm + 1024;
    float2* sdx = (float2*)(sm + 2048);
    float*  sz  = sm + 4096;
    float*  sp  = sm + 5120;
    float*  sDp = sm + 25600;

    const int tid  = threadIdx.x;
    const int lane = tid & 31;
    const int w    = tid >> 5;
    const int cidx = 2 * w + (lane >> 4);
    const int n    = lane & 15;
    const int b    = blockIdx.x >> 7;
    const int d0   = (blockIdx.x & 127) * 16;
    const int d    = d0 + cidx;

    if (tid < 16) sDp[tid] = Dp[d0 + tid];

    const float A = -expf(A_log[d * DSTATE + n]);
    float h = 0.f;
    const int spb = cidx * 20 + n;

    const int sl = tid >> 2;
    const int c0 = (tid & 3) << 2;
    const float4 wd = *reinterpret_cast<const float4*>(w_dt + d0 + c0);
    const float4 bd = *reinterpret_cast<const float4*>(b_dt + d0 + c0);

    for (int t0 = 0; t0 < LSEQ; t0 += 64) {
        {
            size_t base_bc = (size_t)(b * LSEQ + t0) * DSTATE;
            ((float4*)sB)[tid] = ((const float4*)(gB + base_bc))[tid];
            ((float4*)sC)[tid] = ((const float4*)(gC + base_bc))[tid];

            size_t grow = (size_t)(b * LSEQ + t0 + sl);
            float  del  = gdelta[grow];
            float4 xv   = *reinterpret_cast<const float4*>(gxs + grow * DINNER + d0 + c0);
            float4 zv   = *reinterpret_cast<const float4*>(gxz + grow * XZW + DINNER + d0 + c0);

            float sp0 = fmaf(del, wd.x, bd.x);
            float sp1 = fmaf(del, wd.y, bd.y);
            float sp2 = fmaf(del, wd.z, bd.z);
            float sp3 = fmaf(del, wd.w, bd.w);
            sp0 = (sp0 > 30.f) ? sp0 : log1pf(__expf(sp0));
            sp1 = (sp1 > 30.f) ? sp1 : log1pf(__expf(sp1));
            sp2 = (sp2 > 30.f) ? sp2 : log1pf(__expf(sp2));
            sp3 = (sp3 > 30.f) ? sp3 : log1pf(__expf(sp3));

            float2* dsx = sdx + sl * 16 + c0;
            dsx[0] = make_float2(sp0, xv.x);
            dsx[1] = make_float2(sp1, xv.y);
            dsx[2] = make_float2(sp2, xv.z);
            dsx[3] = make_float2(sp3, xv.w);
            *reinterpret_cast<float4*>(sz + sl * 16 + c0) = zv;
        }
        __syncthreads();

#pragma unroll 4
        for (int l = 0; l < 64; ++l) {
            float2 dx = sdx[l * 16 + cidx];
            float  Bv = sB [l * 16 + n];
            float  Cv = sC [l * 16 + n];
            float  a  = __expf(dx.x * A);
            h = fmaf(a, h, dx.x * dx.y * Bv);
            sp[l * 320 + spb] = h * Cv;
        }
        __syncthreads();

        {
            size_t grow = (size_t)(b * LSEQ + t0 + sl);
            float gv[4];
#pragma unroll
            for (int j = 0; j < 4; ++j) {
                int ch = c0 + j;
                const float4* row4 = (const float4*)(sp + sl * 320 + ch * 20);
                float4 r0 = row4[0], r1 = row4[1], r2 = row4[2], r3 = row4[3];
                float s = ((r0.x + r0.y) + (r0.z + r0.w)) + ((r1.x + r1.y) + (r1.z + r1.w))
                        + ((r2.x + r2.y) + (r2.z + r2.w)) + ((r3.x + r3.y) + (r3.z + r3.w));
                float xv = sdx[sl * 16 + ch].y;
                float y  = fmaf(xv, sDp[ch], s);
                float zv = sz[sl * 16 + ch];
                gv[j] = y * silu_f(zv);
            }
            __nv_bfloat16 h0 = __float2bfloat16(gv[0]), h1 = __float2bfloat16(gv[1]);
            __nv_bfloat16 h2 = __float2bfloat16(gv[2]), h3 = __float2bfloat16(gv[3]);
            __nv_bfloat162 ph0 = __halves2bfloat162(h0, h1);
            __nv_bfloat162 ph1 = __halves2bfloat162(h2, h3);
            __nv_bfloat162 pl0 = __halves2bfloat162(
                __float2bfloat16(gv[0] - __bfloat162float(h0)),
                __float2bfloat16(gv[1] - __bfloat162float(h1)));
            __nv_bfloat162 pl1 = __halves2bfloat162(
                __float2bfloat16(gv[2] - __bfloat162float(h2)),
                __float2bfloat16(gv[3] - __bfloat162float(h3)));
            __nv_bfloat162* ph = reinterpret_cast<__nv_bfloat162*>(yh + grow * DINNER + d0 + c0);
            __nv_bfloat162* pl = reinterpret_cast<__nv_bfloat162*>(yl + grow * DINNER + d0 + c0);
            ph[0] = ph0; ph[1] = ph1;
            pl[0] = pl0; pl[1] = pl1;
        }
        __syncthreads();
    }
}

// ============================================================================
// launch
// ============================================================================
extern "C" void kernel_launch(void* const* d_in, const int* in_sizes, int n_in,
                              void* d_out, int out_size)
{
    const float* x     = (const float*)d_in[0];
    const float* W_in  = (const float*)d_in[1];
    const float* convw = (const float*)d_in[2];
    const float* convb = (const float*)d_in[3];
    const float* W_x   = (const float*)d_in[4];
    const float* w_dt  = (const float*)d_in[5];
    const float* b_dt  = (const float*)d_in[6];
    const float* A_log = (const float*)d_in[7];
    const float* Dp    = (const float*)d_in[8];
    const float* W_out = (const float*)d_in[9];
    float* out = (float*)d_out;

    float *p_xz, *p_xs, *p_B, *p_C, *p_delta;
    cudaGetSymbolAddress((void**)&p_xz,    g_xz);
    cudaGetSymbolAddress((void**)&p_xs,    g_xs);
    cudaGetSymbolAddress((void**)&p_B,     g_Bc);
    cudaGetSymbolAddress((void**)&p_C,     g_Cc);
    cudaGetSymbolAddress((void**)&p_delta, g_delta);

    __nv_bfloat16 *xa_h, *xa_l, *w1_h, *w1_l, *ya_h, *ya_l, *w2_h, *w2_l;
    cudaGetSymbolAddress((void**)&xa_h, g_xa_h);
    cudaGetSymbolAddress((void**)&xa_l, g_xa_l);
    cudaGetSymbolAddress((void**)&w1_h, g_w1_h);
    cudaGetSymbolAddress((void**)&w1_l, g_w1_l);
    cudaGetSymbolAddress((void**)&ya_h, g_ya_h);
    cudaGetSymbolAddress((void**)&ya_l, g_ya_l);
    cudaGetSymbolAddress((void**)&w2_h, g_w2_h);
    cudaGetSymbolAddress((void**)&w2_l, g_w2_l);

    constexpr int GSMEM = 2 * STAGE_BYTES;       // 96 KB -> 2 CTAs/SM
    constexpr int SSMEM = SCAN_SMEM_FLOATS * 4;
    cudaFuncSetAttribute((const void*)gemm_mma,
                         cudaFuncAttributeMaxDynamicSharedMemorySize, GSMEM);
    cudaFuncSetAttribute((const void*)scan_k,
                         cudaFuncAttributeMaxDynamicSharedMemorySize, SSMEM);

    // prep: weight transpose+split, x split
    tr_split_k<<<dim3(XZW / 32, DMODEL / 32), 256>>>(W_in, w1_h, w1_l, DMODEL, XZW);
    tr_split_k<<<dim3(DMODEL / 32, DINNER / 32), 256>>>(W_out, w2_h, w2_l, DINNER, DMODEL);
    split_bf16_k<<<(NROWS * DMODEL / 4 + 255) / 256, 256>>>(x, xa_h, xa_l, NROWS * DMODEL / 4);

    // 1. xz = x @ W_in   (128x64 tiles, 2 CTAs/SM)
    gemm_mma<<<dim3(XZW / 64, NROWS / 128), 256, GSMEM>>>(
        xa_h, xa_l, w1_h, w1_l, p_xz, NROWS, XZW, DMODEL);

    // 2. xs = silu(conv(x_) + b)
    conv_silu_k<<<(NROWS / 4) * (DINNER / 4) / 256, 256>>>(p_xz, convw, convb, p_xs);

    // 3. B, C, delta
    bcd_k<<<NROWS / 32, 256>>>(p_xs, W_x, p_B, p_C, p_delta);

    // 4. selective scan (fused softplus, skip, gate, bf16 split)
    scan_k<<<BATCH * (DINNER / 16), 256, SSMEM>>>(
        p_delta, w_dt, b_dt, p_xs, p_xz, p_B, p_C, A_log, Dp, ya_h, ya_l);

    // 5. out = yz @ W_out  (128x64 tiles, 2 CTAs/SM)
    gemm_mma<<<dim3(DMODEL / 64, NROWS / 128), 256, GSMEM>>>(
        ya_h, ya_l, w2_h, w2_l, out, NROWS, DMODEL, DINNER);
}

// round 13
// speedup vs baseline: 1.0483x; 1.0011x over previous
#include <cuda_runtime.h>
#include <cuda_bf16.h>
#include <cstdint>
#include <cmath>

// Problem constants
#define BATCH   2
#define LSEQ    2048
#define DMODEL  1024
#define DINNER  2048
#define DSTATE  16
#define NROWS   (BATCH*LSEQ)          // 4096
#define XZW     (2*DINNER)            // 4096

// ---------------- scratch (static device arrays; no allocation) ------------
__device__ float g_xz   [(size_t)NROWS * XZW];     // x@W_in (x_|z)
__device__ float g_xs   [(size_t)NROWS * DINNER];  // silu(conv(x_))
__device__ float g_Bc   [(size_t)NROWS * DSTATE];
__device__ float g_Cc   [(size_t)NROWS * DSTATE];
__device__ float g_delta[NROWS];

// bf16 split operands for tensor-core GEMMs (aligned for 16B cp.async)
__device__ __align__(128) __nv_bfloat16 g_xa_h[(size_t)NROWS * DMODEL];
__device__ __align__(128) __nv_bfloat16 g_xa_l[(size_t)NROWS * DMODEL];
__device__ __align__(128) __nv_bfloat16 g_w1_h[(size_t)XZW * DMODEL];     // W_in^T  [4096,1024]
__device__ __align__(128) __nv_bfloat16 g_w1_l[(size_t)XZW * DMODEL];
__device__ __align__(128) __nv_bfloat16 g_ya_h[(size_t)NROWS * DINNER];
__device__ __align__(128) __nv_bfloat16 g_ya_l[(size_t)NROWS * DINNER];
__device__ __align__(128) __nv_bfloat16 g_w2_h[(size_t)DMODEL * DINNER];  // W_out^T [1024,2048]
__device__ __align__(128) __nv_bfloat16 g_w2_l[(size_t)DMODEL * DINNER];

// ============================ PTX helpers (sm_100-safe) =====================
__device__ __forceinline__ uint32_t smem_u32(const void* p) {
    uint32_t a;
    asm("{ .reg .u64 t; cvta.to.shared.u64 t, %1; cvt.u32.u64 %0, t; }" : "=r"(a) : "l"(p));
    return a;
}
__device__ __forceinline__ void cp16(uint32_t dst, const void* src) {
    asm volatile("cp.async.cg.shared.global [%0], [%1], 16;" :: "r"(dst), "l"(src));
}
__device__ __forceinline__ void cp_commit() {
    asm volatile("cp.async.commit_group;" ::: "memory");
}
__device__ __forceinline__ void ldsm4(uint32_t* r, uint32_t a) {
    asm volatile("ldmatrix.sync.aligned.m8n8.x4.shared.b16 {%0,%1,%2,%3}, [%4];"
        : "=r"(r[0]), "=r"(r[1]), "=r"(r[2]), "=r"(r[3]) : "r"(a));
}
__device__ __forceinline__ void mma16816(float* d, const uint32_t* a, uint32_t b0, uint32_t b1) {
    asm volatile("mma.sync.aligned.m16n8k16.row.col.f32.bf16.bf16.f32 "
        "{%0,%1,%2,%3},{%4,%5,%6,%7},{%8,%9},{%0,%1,%2,%3};"
        : "+f"(d[0]), "+f"(d[1]), "+f"(d[2]), "+f"(d[3])
        : "r"(a[0]), "r"(a[1]), "r"(a[2]), "r"(a[3]), "r"(b0), "r"(b1));
}
__device__ __forceinline__ float silu_f(float v) {
    return v / (1.f + __expf(-v));
}

// ============================================================================
// Tensor-core GEMM (R12 validated config, unchanged):  C = A @ B^T.
// CTA tile 128x64, K chunks of 64, 2-stage cp.async (96KB -> 2 CTAs/SM),
// 256 threads, warp tile 32x32, 3-term bf16 split accumulation.
// ============================================================================
#define STAGE_BYTES 49152u   // Ah 16K | Al 16K | Bh 8K | Bl 8K

__global__ __launch_bounds__(256, 2) void gemm_mma(
    const __nv_bfloat16* __restrict__ Ah, const __nv_bfloat16* __restrict__ Al,
    const __nv_bfloat16* __restrict__ Bh, const __nv_bfloat16* __restrict__ Bl,
    float* __restrict__ C, int M, int N, int K)
{
    extern __shared__ char smem[];
    const uint32_t sb = smem_u32(smem);

    const int tid  = threadIdx.x;
    const int lane = tid & 31, wid = tid >> 5;
    const int wm   = wid >> 1, wn = wid & 1;
    const int m0   = blockIdx.y * 128, n0 = blockIdx.x * 64;
    const int NC   = K >> 6;

    const int lrow0 = tid >> 3;
    const int lseg  = tid & 7;
    const int lr    = lane & 15;
    const int lc    = lane >> 4;

    float acc[2][4][4];
#pragma unroll
    for (int i = 0; i < 2; ++i)
#pragma unroll
        for (int j = 0; j < 4; ++j)
#pragma unroll
            for (int q = 0; q < 4; ++q) acc[i][j][q] = 0.f;

    auto LOAD = [&](int c) {
        const int kc = c << 6;
        const uint32_t base = sb + (uint32_t)(c & 1) * STAGE_BYTES;
#pragma unroll
        for (int i = 0; i < 4; ++i) {
            int row = lrow0 + i * 32;
            uint32_t ro = (uint32_t)row * 128u + (uint32_t)((lseg ^ (row & 7)) << 4);
            cp16(base + ro,          Ah + (size_t)(m0 + row) * K + kc + lseg * 8);
            cp16(base + 16384u + ro, Al + (size_t)(m0 + row) * K + kc + lseg * 8);
        }
#pragma unroll
        for (int i = 0; i < 2; ++i) {
            int row = lrow0 + i * 32;
            uint32_t ro = (uint32_t)row * 128u + (uint32_t)((lseg ^ (row & 7)) << 4);
            cp16(base + 32768u + ro, Bh + (size_t)(n0 + row) * K + kc + lseg * 8);
            cp16(base + 40960u + ro, Bl + (size_t)(n0 + row) * K + kc + lseg * 8);
        }
        cp_commit();
    };

    LOAD(0);
    if (NC > 1) LOAD(1);

    for (int c = 0; c < NC; ++c) {
        if (c + 1 < NC) asm volatile("cp.async.wait_group 1;" ::: "memory");
        else            asm volatile("cp.async.wait_group 0;" ::: "memory");
        __syncthreads();

        const uint32_t ab = sb + (uint32_t)(c & 1) * STAGE_BYTES;
        const uint32_t bb = ab + 32768u;

#pragma unroll
        for (int ks = 0; ks < 4; ++ks) {
            uint32_t ah[2][4], al[2][4], bh[2][4], bl[2][4];
#pragma unroll
            for (int am = 0; am < 2; ++am) {
                int row = wm * 32 + am * 16 + lr;
                uint32_t c16 = (uint32_t)((ks * 2 + lc) ^ (row & 7));
                uint32_t off = (uint32_t)row * 128u + (c16 << 4);
                ldsm4(ah[am], ab + off);
                ldsm4(al[am], ab + 16384u + off);
            }
#pragma unroll
            for (int nb = 0; nb < 2; ++nb) {
                int row = wn * 32 + nb * 16 + lr;
                uint32_t c16 = (uint32_t)((ks * 2 + lc) ^ (row & 7));
                uint32_t off = (uint32_t)row * 128u + (c16 << 4);
                ldsm4(bh[nb], bb + off);
                ldsm4(bl[nb], bb + 8192u + off);
            }
#pragma unroll
            for (int am = 0; am < 2; ++am)
#pragma unroll
                for (int nb = 0; nb < 2; ++nb)
#pragma unroll
                    for (int h2 = 0; h2 < 2; ++h2)
                        mma16816(acc[am][nb * 2 + h2], ah[am], bh[nb][h2], bh[nb][h2 + 2]);
#pragma unroll
            for (int am = 0; am < 2; ++am)
#pragma unroll
                for (int nb = 0; nb < 2; ++nb)
#pragma unroll
                    for (int h2 = 0; h2 < 2; ++h2)
                        mma16816(acc[am][nb * 2 + h2], ah[am], bl[nb][h2], bl[nb][h2 + 2]);
#pragma unroll
            for (int am = 0; am < 2; ++am)
#pragma unroll
                for (int nb = 0; nb < 2; ++nb)
#pragma unroll
                    for (int h2 = 0; h2 < 2; ++h2)
                        mma16816(acc[am][nb * 2 + h2], al[am], bh[nb][h2], bh[nb][h2 + 2]);
        }
        __syncthreads();
        if (c + 2 < NC) LOAD(c + 2);
    }

    const int er = lane >> 2, ec = (lane & 3) * 2;
#pragma unroll
    for (int am = 0; am < 2; ++am) {
        int row = m0 + wm * 32 + am * 16 + er;
#pragma unroll
        for (int na = 0; na < 4; ++na) {
            int col = n0 + wn * 32 + na * 8 + ec;
            float* d = acc[am][na];
            *reinterpret_cast<float2*>(C + (size_t)row * N + col)       = make_float2(d[0], d[1]);
            *reinterpret_cast<float2*>(C + (size_t)(row + 8) * N + col) = make_float2(d[2], d[3]);
        }
    }
}

// ============================================================================
// Merged prep: one launch does tr_split(W_in), tr_split(W_out), split(x).
// Block ranges: [0,4096) w1 tiles | [4096,6144) w2 tiles | [6144,10240) x split
// ============================================================================
__device__ __forceinline__ void tr_split_body(
    float (*t)[33], const float* __restrict__ W,
    __nv_bfloat16* __restrict__ hi, __nv_bfloat16* __restrict__ lo,
    int K, int N, int k0, int n0)
{
    const int tx = threadIdx.x & 31, ty = threadIdx.x >> 5;
#pragma unroll
    for (int i = 0; i < 4; ++i)
        t[ty + i * 8][tx] = W[(size_t)(k0 + ty + i * 8) * N + n0 + tx];
    __syncthreads();
#pragma unroll
    for (int i = 0; i < 4; ++i) {
        int n = n0 + ty + i * 8;
        float v = t[tx][ty + i * 8];
        __nv_bfloat16 h = __float2bfloat16(v);
        hi[(size_t)n * K + k0 + tx] = h;
        lo[(size_t)n * K + k0 + tx] = __float2bfloat16(v - __bfloat162float(h));
    }
}

__global__ __launch_bounds__(256) void prep_k(
    const float* __restrict__ W_in,  __nv_bfloat16* __restrict__ w1h, __nv_bfloat16* __restrict__ w1l,
    const float* __restrict__ W_out, __nv_bfloat16* __restrict__ w2h, __nv_bfloat16* __restrict__ w2l,
    const float* __restrict__ x,     __nv_bfloat16* __restrict__ xh,  __nv_bfloat16* __restrict__ xl)
{
    __shared__ float t[32][33];
    int b = blockIdx.x;
    if (b < 4096) {
        // W_in: K=DMODEL, N=XZW; grid 128 x 32
        int bx = b & 127, by = b >> 7;
        tr_split_body(t, W_in, w1h, w1l, DMODEL, XZW, by * 32, bx * 32);
    } else if (b < 6144) {
        // W_out: K=DINNER, N=DMODEL; grid 32 x 64
        b -= 4096;
        int bx = b & 31, by = b >> 5;
        tr_split_body(t, W_out, w2h, w2l, DINNER, DMODEL, by * 32, bx * 32);
    } else {
        b -= 6144;
        int i = b * 256 + threadIdx.x;         // < NROWS*DMODEL/4 = 1M exactly
        float4 v = reinterpret_cast<const float4*>(x)[i];
        __nv_bfloat16 h0 = __float2bfloat16(v.x), h1 = __float2bfloat16(v.y);
        __nv_bfloat16 h2 = __float2bfloat16(v.z), h3 = __float2bfloat16(v.w);
        reinterpret_cast<__nv_bfloat162*>(xh)[2 * i]     = __halves2bfloat162(h0, h1);
        reinterpret_cast<__nv_bfloat162*>(xh)[2 * i + 1] = __halves2bfloat162(h2, h3);
        __nv_bfloat16 l0 = __float2bfloat16(v.x - __bfloat162float(h0));
        __nv_bfloat16 l1 = __float2bfloat16(v.y - __bfloat162float(h1));
        __nv_bfloat16 l2 = __float2bfloat16(v.z - __bfloat162float(h2));
        __nv_bfloat16 l3 = __float2bfloat16(v.w - __bfloat162float(h3));
        reinterpret_cast<__nv_bfloat162*>(xl)[2 * i]     = __halves2bfloat162(l0, l1);
        reinterpret_cast<__nv_bfloat162*>(xl)[2 * i + 1] = __halves2bfloat162(l2, l3);
    }
}

// ============================================================================
// Depthwise causal conv (k=4) + bias + SiLU.  4 consecutive l per thread.
// ============================================================================
__global__ __launch_bounds__(256) void conv_silu_k(
    const float* __restrict__ xz, const float* __restrict__ cw,
    const float* __restrict__ cb, float* __restrict__ xs)
{
    int idx  = blockIdx.x * 256 + threadIdx.x;
    int d4   = (idx & (DINNER / 4 - 1)) << 2;
    int rb   = idx >> 9;
    int r0   = rb << 2;
    int l0   = r0 & (LSEQ - 1);

    float4 bias = *reinterpret_cast<const float4*>(cb + d4);
    float4 w0 = reinterpret_cast<const float4*>(cw)[d4 + 0];
    float4 w1 = reinterpret_cast<const float4*>(cw)[d4 + 1];
    float4 w2 = reinterpret_cast<const float4*>(cw)[d4 + 2];
    float4 w3 = reinterpret_cast<const float4*>(cw)[d4 + 3];

    float4 v[7];
#pragma unroll
    for (int j = 0; j < 7; ++j) {
        int l = l0 - 3 + j;
        v[j] = (l >= 0)
             ? *reinterpret_cast<const float4*>(xz + (size_t)(r0 - 3 + j) * XZW + d4)
             : make_float4(0.f, 0.f, 0.f, 0.f);
    }
#pragma unroll
    for (int i = 0; i < 4; ++i) {
        float4 acc = bias;
#pragma unroll
        for (int k = 0; k < 4; ++k) {
            float4 xv = v[i + k];
            acc.x = fmaf((&w0.x)[k], xv.x, acc.x);
            acc.y = fmaf((&w1.x)[k], xv.y, acc.y);
            acc.z = fmaf((&w2.x)[k], xv.z, acc.z);
            acc.w = fmaf((&w3.x)[k], xv.w, acc.w);
        }
        acc.x = silu_f(acc.x); acc.y = silu_f(acc.y);
        acc.z = silu_f(acc.z); acc.w = silu_f(acc.w);
        *reinterpret_cast<float4*>(xs + (size_t)(r0 + i) * DINNER + d4) = acc;
    }
}

// ============================================================================
// bcd = xs @ W_x  (K=2048, N=33) -> B, C, delta   [PROFILED SLOT this round]
// ============================================================================
__global__ __launch_bounds__(256) void bcd_k(
    const float* __restrict__ xs, const float* __restrict__ Wx,
    float* __restrict__ gB, float* __restrict__ gC, float* __restrict__ gdelta)
{
    __shared__ float sX[32 * 33];
    __shared__ float sW[32 * 36];

    const int tid  = threadIdx.x;
    const int row0 = blockIdx.x * 32;
    const int row  = tid & 31;
    const int g    = tid >> 5;

    float acc0 = 0.f, acc1 = 0.f, acc2 = 0.f, acc3 = 0.f, accd = 0.f;

    for (int kc = 0; kc < DINNER; kc += 32) {
        for (int e = tid; e < 32 * 36; e += 256) {
            int k = e / 36, n = e - k * 36;
            sW[e] = (n < 33) ? Wx[(size_t)(kc + k) * 33 + n] : 0.f;
        }
        {
            int r = tid >> 3, c4 = tid & 7;
            float4 v = *(const float4*)(xs + (size_t)(row0 + r) * DINNER + kc + c4 * 4);
            int kk = c4 * 4;
            sX[(kk + 0) * 33 + r] = v.x;
            sX[(kk + 1) * 33 + r] = v.y;
            sX[(kk + 2) * 33 + r] = v.z;
            sX[(kk + 3) * 33 + r] = v.w;
        }
        __syncthreads();
#pragma unroll 8
        for (int k = 0; k < 32; ++k) {
            float  xv = sX[k * 33 + row];
            float4 wv = *(const float4*)(&sW[k * 36 + g * 4]);
            acc0 = fmaf(xv, wv.x, acc0);
            acc1 = fmaf(xv, wv.y, acc1);
            acc2 = fmaf(xv, wv.z, acc2);
            acc3 = fmaf(xv, wv.w, acc3);
            if (g == 0) accd = fmaf(xv, sW[k * 36 + 32], accd);
        }
        __syncthreads();
    }

    const int grow = row0 + row;
    float a[4] = {acc0, acc1, acc2, acc3};
#pragma unroll
    for (int j = 0; j < 4; ++j) {
        int nn = g * 4 + j;
        if (nn < 16) gB[(size_t)grow * 16 + nn]        = a[j];
        else         gC[(size_t)grow * 16 + (nn - 16)] = a[j];
    }
    if (g == 0) gdelta[grow] = accd;
}

// ============================================================================
// Selective scan: interleaved (B,C) float2 in the serial loop (1 LDS.64
// instead of 2 LDS.32 per step), vectorized staging/epilogue, smem partials.
// smem (floats): sBC 2048 | sdx 2048 | sz 1024 | sp 20480 | sDp 16
// ============================================================================
#define SCAN_SMEM_FLOATS (25600 + 16)

__global__ __launch_bounds__(256) void scan_k(
    const float* __restrict__ gdelta, const float* __restrict__ w_dt,
    const float* __restrict__ b_dt,
    const float* __restrict__ gxs,  const float* __restrict__ gxz,
    const float* __restrict__ gB,   const float* __restrict__ gC,
    const float* __restrict__ A_log, const float* __restrict__ Dp,
    __nv_bfloat16* __restrict__ yh, __nv_bfloat16* __restrict__ yl)
{
    extern __shared__ float sm[];
    float2* sBC = (float2*)sm;             // [l*16+n] -> (B, C)
    float2* sdx = (float2*)(sm + 2048);    // [l*16+d] -> (dt, x)
    float*  sz  = sm + 4096;
    float*  sp  = sm + 5120;
    float*  sDp = sm + 25600;

    const int tid  = threadIdx.x;
    const int lane = tid & 31;
    const int w    = tid >> 5;
    const int cidx = 2 * w + (lane >> 4);
    const int n    = lane & 15;
    const int b    = blockIdx.x >> 7;
    const int d0   = (blockIdx.x & 127) * 16;
    const int d    = d0 + cidx;

    if (tid < 16) sDp[tid] = Dp[d0 + tid];

    const float A = -expf(A_log[d * DSTATE + n]);
    float h = 0.f;
    const int spb = cidx * 20 + n;

    const int sl = tid >> 2;
    const int c0 = (tid & 3) << 2;
    const float4 wd = *reinterpret_cast<const float4*>(w_dt + d0 + c0);
    const float4 bd = *reinterpret_cast<const float4*>(b_dt + d0 + c0);

    for (int t0 = 0; t0 < LSEQ; t0 += 64) {
        {
            size_t base_bc = (size_t)(b * LSEQ + t0) * DSTATE;
            float4 bv = ((const float4*)(gB + base_bc))[tid];
            float4 cv = ((const float4*)(gC + base_bc))[tid];
            float2* dst = sBC + tid * 4;
            dst[0] = make_float2(bv.x, cv.x);
            dst[1] = make_float2(bv.y, cv.y);
            dst[2] = make_float2(bv.z, cv.z);
            dst[3] = make_float2(bv.w, cv.w);

            size_t grow = (size_t)(b * LSEQ + t0 + sl);
            float  del  = gdelta[grow];
            float4 xv   = *reinterpret_cast<const float4*>(gxs + grow * DINNER + d0 + c0);
            float4 zv   = *reinterpret_cast<const float4*>(gxz + grow * XZW + DINNER + d0 + c0);

            float sp0 = fmaf(del, wd.x, bd.x);
            float sp1 = fmaf(del, wd.y, bd.y);
            float sp2 = fmaf(del, wd.z, bd.z);
            float sp3 = fmaf(del, wd.w, bd.w);
            sp0 = (sp0 > 30.f) ? sp0 : log1pf(__expf(sp0));
            sp1 = (sp1 > 30.f) ? sp1 : log1pf(__expf(sp1));
            sp2 = (sp2 > 30.f) ? sp2 : log1pf(__expf(sp2));
            sp3 = (sp3 > 30.f) ? sp3 : log1pf(__expf(sp3));

            float2* dsx = sdx + sl * 16 + c0;
            dsx[0] = make_float2(sp0, xv.x);
            dsx[1] = make_float2(sp1, xv.y);
            dsx[2] = make_float2(sp2, xv.z);
            dsx[3] = make_float2(sp3, xv.w);
            *reinterpret_cast<float4*>(sz + sl * 16 + c0) = zv;
        }
        __syncthreads();

#pragma unroll 4
        for (int l = 0; l < 64; ++l) {
            float2 dx = sdx[l * 16 + cidx];   // dt, x
            float2 bc = sBC[l * 16 + n];      // B, C
            float  a  = __expf(dx.x * A);
            h = fmaf(a, h, dx.x * dx.y * bc.x);
            sp[l * 320 + spb] = h * bc.y;
        }
        __syncthreads();

        {
            size_t grow = (size_t)(b * LSEQ + t0 + sl);
            float gv[4];
#pragma unroll
            for (int j = 0; j < 4; ++j) {
                int ch = c0 + j;
                const float4* row4 = (const float4*)(sp + sl * 320 + ch * 20);
                float4 r0 = row4[0], r1 = row4[1], r2 = row4[2], r3 = row4[3];
                float s = ((r0.x + r0.y) + (r0.z + r0.w)) + ((r1.x + r1.y) + (r1.z + r1.w))
                        + ((r2.x + r2.y) + (r2.z + r2.w)) + ((r3.x + r3.y) + (r3.z + r3.w));
                float xv = sdx[sl * 16 + ch].y;
                float y  = fmaf(xv, sDp[ch], s);
                float zv = sz[sl * 16 + ch];
                gv[j] = y * silu_f(zv);
            }
            __nv_bfloat16 h0 = __float2bfloat16(gv[0]), h1 = __float2bfloat16(gv[1]);
            __nv_bfloat16 h2 = __float2bfloat16(gv[2]), h3 = __float2bfloat16(gv[3]);
            __nv_bfloat162 ph0 = __halves2bfloat162(h0, h1);
            __nv_bfloat162 ph1 = __halves2bfloat162(h2, h3);
            __nv_bfloat162 pl0 = __halves2bfloat162(
                __float2bfloat16(gv[0] - __bfloat162float(h0)),
                __float2bfloat16(gv[1] - __bfloat162float(h1)));
            __nv_bfloat162 pl1 = __halves2bfloat162(
                __float2bfloat16(gv[2] - __bfloat162float(h2)),
                __float2bfloat16(gv[3] - __bfloat162float(h3)));
            __nv_bfloat162* ph = reinterpret_cast<__nv_bfloat162*>(yh + grow * DINNER + d0 + c0);
            __nv_bfloat162* pl = reinterpret_cast<__nv_bfloat162*>(yl + grow * DINNER + d0 + c0);
            ph[0] = ph0; ph[1] = ph1;
            pl[0] = pl0; pl[1] = pl1;
        }
        __syncthreads();
    }
}

// ============================================================================
// launch — order matters: 4th launch (bcd_k) is the ncu-captured slot.
// ============================================================================
extern "C" void kernel_launch(void* const* d_in, const int* in_sizes, int n_in,
                              void* d_out, int out_size)
{
    const float* x     = (const float*)d_in[0];
    const float* W_in  = (const float*)d_in[1];
    const float* convw = (const float*)d_in[2];
    const float* convb = (const float*)d_in[3];
    const float* W_x   = (const float*)d_in[4];
    const float* w_dt  = (const float*)d_in[5];
    const float* b_dt  = (const float*)d_in[6];
    const float* A_log = (const float*)d_in[7];
    const float* Dp    = (const float*)d_in[8];
    const float* W_out = (const float*)d_in[9];
    float* out = (float*)d_out;

    float *p_xz, *p_xs, *p_B, *p_C, *p_delta;
    cudaGetSymbolAddress((void**)&p_xz,    g_xz);
    cudaGetSymbolAddress((void**)&p_xs,    g_xs);
    cudaGetSymbolAddress((void**)&p_B,     g_Bc);
    cudaGetSymbolAddress((void**)&p_C,     g_Cc);
    cudaGetSymbolAddress((void**)&p_delta, g_delta);

    __nv_bfloat16 *xa_h, *xa_l, *w1_h, *w1_l, *ya_h, *ya_l, *w2_h, *w2_l;
    cudaGetSymbolAddress((void**)&xa_h, g_xa_h);
    cudaGetSymbolAddress((void**)&xa_l, g_xa_l);
    cudaGetSymbolAddress((void**)&w1_h, g_w1_h);
    cudaGetSymbolAddress((void**)&w1_l, g_w1_l);
    cudaGetSymbolAddress((void**)&ya_h, g_ya_h);
    cudaGetSymbolAddress((void**)&ya_l, g_ya_l);
    cudaGetSymbolAddress((void**)&w2_h, g_w2_h);
    cudaGetSymbolAddress((void**)&w2_l, g_w2_l);

    constexpr int GSMEM = 2 * STAGE_BYTES;       // 96 KB -> 2 CTAs/SM
    constexpr int SSMEM = SCAN_SMEM_FLOATS * 4;
    cudaFuncSetAttribute((const void*)gemm_mma,
                         cudaFuncAttributeMaxDynamicSharedMemorySize, GSMEM);
    cudaFuncSetAttribute((const void*)scan_k,
                         cudaFuncAttributeMaxDynamicSharedMemorySize, SSMEM);

    // #1: merged prep (w1 transpose-split | w2 transpose-split | x split)
    prep_k<<<10240, 256>>>(W_in, w1_h, w1_l, W_out, w2_h, w2_l, x, xa_h, xa_l);

    // #2: xz = x @ W_in
    gemm_mma<<<dim3(XZW / 64, NROWS / 128), 256, GSMEM>>>(
        xa_h, xa_l, w1_h, w1_l, p_xz, NROWS, XZW, DMODEL);

    // #3: xs = silu(conv(x_) + b)
    conv_silu_k<<<(NROWS / 4) * (DINNER / 4) / 256, 256>>>(p_xz, convw, convb, p_xs);

    // #4: B, C, delta   <-- profiled slot
    bcd_k<<<NROWS / 32, 256>>>(p_xs, W_x, p_B, p_C, p_delta);

    // #5: selective scan (fused softplus, skip, gate, bf16 split)
    scan_k<<<BATCH * (DINNER / 16), 256, SSMEM>>>(
        p_delta, w_dt, b_dt, p_xs, p_xz, p_B, p_C, A_log, Dp, ya_h, ya_l);

    // #6: out = yz @ W_out
    gemm_mma<<<dim3(DMODEL / 64, NROWS / 128), 256, GSMEM>>>(
        ya_h, ya_l, w2_h, w2_l, out, NROWS, DMODEL, DINNER);
}

// round 14
// speedup vs baseline: 1.2425x; 1.1852x over previous
#include <cuda_runtime.h>
#include <cuda_bf16.h>
#include <cstdint>
#include <cmath>

// Problem constants
#define BATCH   2
#define LSEQ    2048
#define DMODEL  1024
#define DINNER  2048
#define DSTATE  16
#define NROWS   (BATCH*LSEQ)          // 4096
#define XZW     (2*DINNER)            // 4096
#define KSPLIT  8                     // bcd split-K factor

// ---------------- scratch (static device arrays; no allocation) ------------
__device__ float g_xz   [(size_t)NROWS * XZW];     // x@W_in (x_|z)
__device__ float g_xs   [(size_t)NROWS * DINNER];  // silu(conv(x_))
__device__ float g_Bc   [(size_t)NROWS * DSTATE];
__device__ float g_Cc   [(size_t)NROWS * DSTATE];
__device__ float g_delta[NROWS];
__device__ float g_part [(size_t)KSPLIT * NROWS * 36];   // bcd split-K partials

// bf16 split operands for tensor-core GEMMs (aligned for 16B cp.async)
__device__ __align__(128) __nv_bfloat16 g_xa_h[(size_t)NROWS * DMODEL];
__device__ __align__(128) __nv_bfloat16 g_xa_l[(size_t)NROWS * DMODEL];
__device__ __align__(128) __nv_bfloat16 g_w1_h[(size_t)XZW * DMODEL];     // W_in^T  [4096,1024]
__device__ __align__(128) __nv_bfloat16 g_w1_l[(size_t)XZW * DMODEL];
__device__ __align__(128) __nv_bfloat16 g_ya_h[(size_t)NROWS * DINNER];
__device__ __align__(128) __nv_bfloat16 g_ya_l[(size_t)NROWS * DINNER];
__device__ __align__(128) __nv_bfloat16 g_w2_h[(size_t)DMODEL * DINNER];  // W_out^T [1024,2048]
__device__ __align__(128) __nv_bfloat16 g_w2_l[(size_t)DMODEL * DINNER];

// ============================ PTX helpers (sm_100-safe) =====================
__device__ __forceinline__ uint32_t smem_u32(const void* p) {
    uint32_t a;
    asm("{ .reg .u64 t; cvta.to.shared.u64 t, %1; cvt.u32.u64 %0, t; }" : "=r"(a) : "l"(p));
    return a;
}
__device__ __forceinline__ void cp16(uint32_t dst, const void* src) {
    asm volatile("cp.async.cg.shared.global [%0], [%1], 16;" :: "r"(dst), "l"(src));
}
__device__ __forceinline__ void cp_commit() {
    asm volatile("cp.async.commit_group;" ::: "memory");
}
__device__ __forceinline__ void ldsm4(uint32_t* r, uint32_t a) {
    asm volatile("ldmatrix.sync.aligned.m8n8.x4.shared.b16 {%0,%1,%2,%3}, [%4];"
        : "=r"(r[0]), "=r"(r[1]), "=r"(r[2]), "=r"(r[3]) : "r"(a));
}
__device__ __forceinline__ void mma16816(float* d, const uint32_t* a, uint32_t b0, uint32_t b1) {
    asm volatile("mma.sync.aligned.m16n8k16.row.col.f32.bf16.bf16.f32 "
        "{%0,%1,%2,%3},{%4,%5,%6,%7},{%8,%9},{%0,%1,%2,%3};"
        : "+f"(d[0]), "+f"(d[1]), "+f"(d[2]), "+f"(d[3])
        : "r"(a[0]), "r"(a[1]), "r"(a[2]), "r"(a[3]), "r"(b0), "r"(b1));
}
__device__ __forceinline__ float silu_f(float v) {
    return v / (1.f + __expf(-v));
}

// ============================================================================
// Tensor-core GEMM (R12 validated config, unchanged):  C = A @ B^T.
// CTA tile 128x64, K chunks of 64, 2-stage cp.async (96KB -> 2 CTAs/SM),
// 256 threads, warp tile 32x32, 3-term bf16 split accumulation.
// ============================================================================
#define STAGE_BYTES 49152u   // Ah 16K | Al 16K | Bh 8K | Bl 8K

__global__ __launch_bounds__(256, 2) void gemm_mma(
    const __nv_bfloat16* __restrict__ Ah, const __nv_bfloat16* __restrict__ Al,
    const __nv_bfloat16* __restrict__ Bh, const __nv_bfloat16* __restrict__ Bl,
    float* __restrict__ C, int M, int N, int K)
{
    extern __shared__ char smem[];
    const uint32_t sb = smem_u32(smem);

    const int tid  = threadIdx.x;
    const int lane = tid & 31, wid = tid >> 5;
    const int wm   = wid >> 1, wn = wid & 1;
    const int m0   = blockIdx.y * 128, n0 = blockIdx.x * 64;
    const int NC   = K >> 6;

    const int lrow0 = tid >> 3;
    const int lseg  = tid & 7;
    const int lr    = lane & 15;
    const int lc    = lane >> 4;

    float acc[2][4][4];
#pragma unroll
    for (int i = 0; i < 2; ++i)
#pragma unroll
        for (int j = 0; j < 4; ++j)
#pragma unroll
            for (int q = 0; q < 4; ++q) acc[i][j][q] = 0.f;

    auto LOAD = [&](int c) {
        const int kc = c << 6;
        const uint32_t base = sb + (uint32_t)(c & 1) * STAGE_BYTES;
#pragma unroll
        for (int i = 0; i < 4; ++i) {
            int row = lrow0 + i * 32;
            uint32_t ro = (uint32_t)row * 128u + (uint32_t)((lseg ^ (row & 7)) << 4);
            cp16(base + ro,          Ah + (size_t)(m0 + row) * K + kc + lseg * 8);
            cp16(base + 16384u + ro, Al + (size_t)(m0 + row) * K + kc + lseg * 8);
        }
#pragma unroll
        for (int i = 0; i < 2; ++i) {
            int row = lrow0 + i * 32;
            uint32_t ro = (uint32_t)row * 128u + (uint32_t)((lseg ^ (row & 7)) << 4);
            cp16(base + 32768u + ro, Bh + (size_t)(n0 + row) * K + kc + lseg * 8);
            cp16(base + 40960u + ro, Bl + (size_t)(n0 + row) * K + kc + lseg * 8);
        }
        cp_commit();
    };

    LOAD(0);
    if (NC > 1) LOAD(1);

    for (int c = 0; c < NC; ++c) {
        if (c + 1 < NC) asm volatile("cp.async.wait_group 1;" ::: "memory");
        else            asm volatile("cp.async.wait_group 0;" ::: "memory");
        __syncthreads();

        const uint32_t ab = sb + (uint32_t)(c & 1) * STAGE_BYTES;
        const uint32_t bb = ab + 32768u;

#pragma unroll
        for (int ks = 0; ks < 4; ++ks) {
            uint32_t ah[2][4], al[2][4], bh[2][4], bl[2][4];
#pragma unroll
            for (int am = 0; am < 2; ++am) {
                int row = wm * 32 + am * 16 + lr;
                uint32_t c16 = (uint32_t)((ks * 2 + lc) ^ (row & 7));
                uint32_t off = (uint32_t)row * 128u + (c16 << 4);
                ldsm4(ah[am], ab + off);
                ldsm4(al[am], ab + 16384u + off);
            }
#pragma unroll
            for (int nb = 0; nb < 2; ++nb) {
                int row = wn * 32 + nb * 16 + lr;
                uint32_t c16 = (uint32_t)((ks * 2 + lc) ^ (row & 7));
                uint32_t off = (uint32_t)row * 128u + (c16 << 4);
                ldsm4(bh[nb], bb + off);
                ldsm4(bl[nb], bb + 8192u + off);
            }
#pragma unroll
            for (int am = 0; am < 2; ++am)
#pragma unroll
                for (int nb = 0; nb < 2; ++nb)
#pragma unroll
                    for (int h2 = 0; h2 < 2; ++h2)
                        mma16816(acc[am][nb * 2 + h2], ah[am], bh[nb][h2], bh[nb][h2 + 2]);
#pragma unroll
            for (int am = 0; am < 2; ++am)
#pragma unroll
                for (int nb = 0; nb < 2; ++nb)
#pragma unroll
                    for (int h2 = 0; h2 < 2; ++h2)
                        mma16816(acc[am][nb * 2 + h2], ah[am], bl[nb][h2], bl[nb][h2 + 2]);
#pragma unroll
            for (int am = 0; am < 2; ++am)
#pragma unroll
                for (int nb = 0; nb < 2; ++nb)
#pragma unroll
                    for (int h2 = 0; h2 < 2; ++h2)
                        mma16816(acc[am][nb * 2 + h2], al[am], bh[nb][h2], bh[nb][h2 + 2]);
        }
        __syncthreads();
        if (c + 2 < NC) LOAD(c + 2);
    }

    const int er = lane >> 2, ec = (lane & 3) * 2;
#pragma unroll
    for (int am = 0; am < 2; ++am) {
        int row = m0 + wm * 32 + am * 16 + er;
#pragma unroll
        for (int na = 0; na < 4; ++na) {
            int col = n0 + wn * 32 + na * 8 + ec;
            float* d = acc[am][na];
            *reinterpret_cast<float2*>(C + (size_t)row * N + col)       = make_float2(d[0], d[1]);
            *reinterpret_cast<float2*>(C + (size_t)(row + 8) * N + col) = make_float2(d[2], d[3]);
        }
    }
}

// ============================================================================
// Merged prep: tr_split(W_in) | tr_split(W_out) | split(x) in one launch
// ============================================================================
__device__ __forceinline__ void tr_split_body(
    float (*t)[33], const float* __restrict__ W,
    __nv_bfloat16* __restrict__ hi, __nv_bfloat16* __restrict__ lo,
    int K, int N, int k0, int n0)
{
    const int tx = threadIdx.x & 31, ty = threadIdx.x >> 5;
#pragma unroll
    for (int i = 0; i < 4; ++i)
        t[ty + i * 8][tx] = W[(size_t)(k0 + ty + i * 8) * N + n0 + tx];
    __syncthreads();
#pragma unroll
    for (int i = 0; i < 4; ++i) {
        int n = n0 + ty + i * 8;
        float v = t[tx][ty + i * 8];
        __nv_bfloat16 h = __float2bfloat16(v);
        hi[(size_t)n * K + k0 + tx] = h;
        lo[(size_t)n * K + k0 + tx] = __float2bfloat16(v - __bfloat162float(h));
    }
}

__global__ __launch_bounds__(256) void prep_k(
    const float* __restrict__ W_in,  __nv_bfloat16* __restrict__ w1h, __nv_bfloat16* __restrict__ w1l,
    const float* __restrict__ W_out, __nv_bfloat16* __restrict__ w2h, __nv_bfloat16* __restrict__ w2l,
    const float* __restrict__ x,     __nv_bfloat16* __restrict__ xh,  __nv_bfloat16* __restrict__ xl)
{
    __shared__ float t[32][33];
    int b = blockIdx.x;
    if (b < 4096) {
        int bx = b & 127, by = b >> 7;
        tr_split_body(t, W_in, w1h, w1l, DMODEL, XZW, by * 32, bx * 32);
    } else if (b < 6144) {
        b -= 4096;
        int bx = b & 31, by = b >> 5;
        tr_split_body(t, W_out, w2h, w2l, DINNER, DMODEL, by * 32, bx * 32);
    } else {
        b -= 6144;
        int i = b * 256 + threadIdx.x;
        float4 v = reinterpret_cast<const float4*>(x)[i];
        __nv_bfloat16 h0 = __float2bfloat16(v.x), h1 = __float2bfloat16(v.y);
        __nv_bfloat16 h2 = __float2bfloat16(v.z), h3 = __float2bfloat16(v.w);
        reinterpret_cast<__nv_bfloat162*>(xh)[2 * i]     = __halves2bfloat162(h0, h1);
        reinterpret_cast<__nv_bfloat162*>(xh)[2 * i + 1] = __halves2bfloat162(h2, h3);
        __nv_bfloat16 l0 = __float2bfloat16(v.x - __bfloat162float(h0));
        __nv_bfloat16 l1 = __float2bfloat16(v.y - __bfloat162float(h1));
        __nv_bfloat16 l2 = __float2bfloat16(v.z - __bfloat162float(h2));
        __nv_bfloat16 l3 = __float2bfloat16(v.w - __bfloat162float(h3));
        reinterpret_cast<__nv_bfloat162*>(xl)[2 * i]     = __halves2bfloat162(l0, l1);
        reinterpret_cast<__nv_bfloat162*>(xl)[2 * i + 1] = __halves2bfloat162(l2, l3);
    }
}

// ============================================================================
// Depthwise causal conv (k=4) + bias + SiLU.  4 consecutive l per thread.
// ============================================================================
__global__ __launch_bounds__(256) void conv_silu_k(
    const float* __restrict__ xz, const float* __restrict__ cw,
    const float* __restrict__ cb, float* __restrict__ xs)
{
    int idx  = blockIdx.x * 256 + threadIdx.x;
    int d4   = (idx & (DINNER / 4 - 1)) << 2;
    int rb   = idx >> 9;
    int r0   = rb << 2;
    int l0   = r0 & (LSEQ - 1);

    float4 bias = *reinterpret_cast<const float4*>(cb + d4);
    float4 w0 = reinterpret_cast<const float4*>(cw)[d4 + 0];
    float4 w1 = reinterpret_cast<const float4*>(cw)[d4 + 1];
    float4 w2 = reinterpret_cast<const float4*>(cw)[d4 + 2];
    float4 w3 = reinterpret_cast<const float4*>(cw)[d4 + 3];

    float4 v[7];
#pragma unroll
    for (int j = 0; j < 7; ++j) {
        int l = l0 - 3 + j;
        v[j] = (l >= 0)
             ? *reinterpret_cast<const float4*>(xz + (size_t)(r0 - 3 + j) * XZW + d4)
             : make_float4(0.f, 0.f, 0.f, 0.f);
    }
#pragma unroll
    for (int i = 0; i < 4; ++i) {
        float4 acc = bias;
#pragma unroll
        for (int k = 0; k < 4; ++k) {
            float4 xv = v[i + k];
            acc.x = fmaf((&w0.x)[k], xv.x, acc.x);
            acc.y = fmaf((&w1.x)[k], xv.y, acc.y);
            acc.z = fmaf((&w2.x)[k], xv.z, acc.z);
            acc.w = fmaf((&w3.x)[k], xv.w, acc.w);
        }
        acc.x = silu_f(acc.x); acc.y = silu_f(acc.y);
        acc.z = silu_f(acc.z); acc.w = silu_f(acc.w);
        *reinterpret_cast<float4*>(xs + (size_t)(r0 + i) * DINNER + d4) = acc;
    }
}

// ============================================================================
// bcd split-K: partial[ks][row][n] = xs[row, ks*256:(ks+1)*256] @ Wx chunk.
// grid (128 row-blocks, KSPLIT).  8 chunk-iters per CTA (was 64).
// ============================================================================
__global__ __launch_bounds__(256) void bcd_k(
    const float* __restrict__ xs, const float* __restrict__ Wx,
    float* __restrict__ part)
{
    __shared__ float sX[32 * 33];
    __shared__ float sW[32 * 36];

    const int tid  = threadIdx.x;
    const int row0 = blockIdx.x * 32;
    const int ks   = blockIdx.y;
    const int kb   = ks * (DINNER / KSPLIT);
    const int row  = tid & 31;
    const int g    = tid >> 5;

    float acc0 = 0.f, acc1 = 0.f, acc2 = 0.f, acc3 = 0.f, accd = 0.f;

    for (int kc = kb; kc < kb + DINNER / KSPLIT; kc += 32) {
        for (int e = tid; e < 32 * 36; e += 256) {
            int k = e / 36, n = e - k * 36;
            sW[e] = (n < 33) ? Wx[(size_t)(kc + k) * 33 + n] : 0.f;
        }
        {
            int r = tid >> 3, c4 = tid & 7;
            float4 v = *(const float4*)(xs + (size_t)(row0 + r) * DINNER + kc + c4 * 4);
            int kk = c4 * 4;
            sX[(kk + 0) * 33 + r] = v.x;
            sX[(kk + 1) * 33 + r] = v.y;
            sX[(kk + 2) * 33 + r] = v.z;
            sX[(kk + 3) * 33 + r] = v.w;
        }
        __syncthreads();
#pragma unroll 8
        for (int k = 0; k < 32; ++k) {
            float  xv = sX[k * 33 + row];
            float4 wv = *(const float4*)(&sW[k * 36 + g * 4]);
            acc0 = fmaf(xv, wv.x, acc0);
            acc1 = fmaf(xv, wv.y, acc1);
            acc2 = fmaf(xv, wv.z, acc2);
            acc3 = fmaf(xv, wv.w, acc3);
            if (g == 0) accd = fmaf(xv, sW[k * 36 + 32], accd);
        }
        __syncthreads();
    }

    float* dst = part + ((size_t)ks * NROWS + row0 + row) * 36;
    float a[4] = {acc0, acc1, acc2, acc3};
#pragma unroll
    for (int j = 0; j < 4; ++j) dst[g * 4 + j] = a[j];
    if (g == 0) dst[32] = accd;
}

// Reduce the KSPLIT partials -> gB, gC, gdelta (fixed order: deterministic)
__global__ __launch_bounds__(256) void bcd_red(
    const float* __restrict__ part,
    float* __restrict__ gB, float* __restrict__ gC, float* __restrict__ gdelta)
{
    int idx = blockIdx.x * 256 + threadIdx.x;      // < 4096*33
    if (idx >= NROWS * 33) return;
    int row = idx / 33, n = idx - row * 33;
    float s = 0.f;
#pragma unroll
    for (int k = 0; k < KSPLIT; ++k)
        s += part[((size_t)k * NROWS + row) * 36 + n];
    if (n < 16)       gB[(size_t)row * 16 + n]        = s;
    else if (n < 32)  gC[(size_t)row * 16 + (n - 16)] = s;
    else              gdelta[row]                     = s;
}

// ============================================================================
// Selective scan (R13 config): interleaved (B,C), vectorized staging/epilogue,
// smem partials, fused softplus + skip + gate + bf16 split.
// ============================================================================
#define SCAN_SMEM_FLOATS (25600 + 16)

__global__ __launch_bounds__(256) void scan_k(
    const float* __restrict__ gdelta, const float* __restrict__ w_dt,
    const float* __restrict__ b_dt,
    const float* __restrict__ gxs,  const float* __restrict__ gxz,
    const float* __restrict__ gB,   const float* __restrict__ gC,
    const float* __restrict__ A_log, const float* __restrict__ Dp,
    __nv_bfloat16* __restrict__ yh, __nv_bfloat16* __restrict__ yl)
{
    extern __shared__ float sm[];
    float2* sBC = (float2*)sm;
    float2* sdx = (float2*)(sm + 2048);
    float*  sz  = sm + 4096;
    float*  sp  = sm + 5120;
    float*  sDp = sm + 25600;

    const int tid  = threadIdx.x;
    const int lane = tid & 31;
    const int w    = tid >> 5;
    const int cidx = 2 * w + (lane >> 4);
    const int n    = lane & 15;
    const int b    = blockIdx.x >> 7;
    const int d0   = (blockIdx.x & 127) * 16;
    const int d    = d0 + cidx;

    if (tid < 16) sDp[tid] = Dp[d0 + tid];

    const float A = -expf(A_log[d * DSTATE + n]);
    float h = 0.f;
    const int spb = cidx * 20 + n;

    const int sl = tid >> 2;
    const int c0 = (tid & 3) << 2;
    const float4 wd = *reinterpret_cast<const float4*>(w_dt + d0 + c0);
    const float4 bd = *reinterpret_cast<const float4*>(b_dt + d0 + c0);

    for (int t0 = 0; t0 < LSEQ; t0 += 64) {
        {
            size_t base_bc = (size_t)(b * LSEQ + t0) * DSTATE;
            float4 bv = ((const float4*)(gB + base_bc))[tid];
            float4 cv = ((const float4*)(gC + base_bc))[tid];
            float2* dst = sBC + tid * 4;
            dst[0] = make_float2(bv.x, cv.x);
            dst[1] = make_float2(bv.y, cv.y);
            dst[2] = make_float2(bv.z, cv.z);
            dst[3] = make_float2(bv.w, cv.w);

            size_t grow = (size_t)(b * LSEQ + t0 + sl);
            float  del  = gdelta[grow];
            float4 xv   = *reinterpret_cast<const float4*>(gxs + grow * DINNER + d0 + c0);
            float4 zv   = *reinterpret_cast<const float4*>(gxz + grow * XZW + DINNER + d0 + c0);

            float sp0 = fmaf(del, wd.x, bd.x);
            float sp1 = fmaf(del, wd.y, bd.y);
            float sp2 = fmaf(del, wd.z, bd.z);
            float sp3 = fmaf(del, wd.w, bd.w);
            sp0 = (sp0 > 30.f) ? sp0 : log1pf(__expf(sp0));
            sp1 = (sp1 > 30.f) ? sp1 : log1pf(__expf(sp1));
            sp2 = (sp2 > 30.f) ? sp2 : log1pf(__expf(sp2));
            sp3 = (sp3 > 30.f) ? sp3 : log1pf(__expf(sp3));

            float2* dsx = sdx + sl * 16 + c0;
            dsx[0] = make_float2(sp0, xv.x);
            dsx[1] = make_float2(sp1, xv.y);
            dsx[2] = make_float2(sp2, xv.z);
            dsx[3] = make_float2(sp3, xv.w);
            *reinterpret_cast<float4*>(sz + sl * 16 + c0) = zv;
        }
        __syncthreads();

#pragma unroll 4
        for (int l = 0; l < 64; ++l) {
            float2 dx = sdx[l * 16 + cidx];
            float2 bc = sBC[l * 16 + n];
            float  a  = __expf(dx.x * A);
            h = fmaf(a, h, dx.x * dx.y * bc.x);
            sp[l * 320 + spb] = h * bc.y;
        }
        __syncthreads();

        {
            size_t grow = (size_t)(b * LSEQ + t0 + sl);
            float gv[4];
#pragma unroll
            for (int j = 0; j < 4; ++j) {
                int ch = c0 + j;
                const float4* row4 = (const float4*)(sp + sl * 320 + ch * 20);
                float4 r0 = row4[0], r1 = row4[1], r2 = row4[2], r3 = row4[3];
                float s = ((r0.x + r0.y) + (r0.z + r0.w)) + ((r1.x + r1.y) + (r1.z + r1.w))
                        + ((r2.x + r2.y) + (r2.z + r2.w)) + ((r3.x + r3.y) + (r3.z + r3.w));
                float xv = sdx[sl * 16 + ch].y;
                float y  = fmaf(xv, sDp[ch], s);
                float zv = sz[sl * 16 + ch];
                gv[j] = y * silu_f(zv);
            }
            __nv_bfloat16 h0 = __float2bfloat16(gv[0]), h1 = __float2bfloat16(gv[1]);
            __nv_bfloat16 h2 = __float2bfloat16(gv[2]), h3 = __float2bfloat16(gv[3]);
            __nv_bfloat162 ph0 = __halves2bfloat162(h0, h1);
            __nv_bfloat162 ph1 = __halves2bfloat162(h2, h3);
            __nv_bfloat162 pl0 = __halves2bfloat162(
                __float2bfloat16(gv[0] - __bfloat162float(h0)),
                __float2bfloat16(gv[1] - __bfloat162float(h1)));
            __nv_bfloat162 pl1 = __halves2bfloat162(
                __float2bfloat16(gv[2] - __bfloat162float(h2)),
                __float2bfloat16(gv[3] - __bfloat162float(h3)));
            __nv_bfloat162* ph = reinterpret_cast<__nv_bfloat162*>(yh + grow * DINNER + d0 + c0);
            __nv_bfloat162* pl = reinterpret_cast<__nv_bfloat162*>(yl + grow * DINNER + d0 + c0);
            ph[0] = ph0; ph[1] = ph1;
            pl[0] = pl0; pl[1] = pl1;
        }
        __syncthreads();
    }
}

// ============================================================================
// launch — the 4th launch is the ncu-profiled slot (bcd_k split-K).
// ============================================================================
extern "C" void kernel_launch(void* const* d_in, const int* in_sizes, int n_in,
                              void* d_out, int out_size)
{
    const float* x     = (const float*)d_in[0];
    const float* W_in  = (const float*)d_in[1];
    const float* convw = (const float*)d_in[2];
    const float* convb = (const float*)d_in[3];
    const float* W_x   = (const float*)d_in[4];
    const float* w_dt  = (const float*)d_in[5];
    const float* b_dt  = (const float*)d_in[6];
    const float* A_log = (const float*)d_in[7];
    const float* Dp    = (const float*)d_in[8];
    const float* W_out = (const float*)d_in[9];
    float* out = (float*)d_out;

    float *p_xz, *p_xs, *p_B, *p_C, *p_delta, *p_part;
    cudaGetSymbolAddress((void**)&p_xz,    g_xz);
    cudaGetSymbolAddress((void**)&p_xs,    g_xs);
    cudaGetSymbolAddress((void**)&p_B,     g_Bc);
    cudaGetSymbolAddress((void**)&p_C,     g_Cc);
    cudaGetSymbolAddress((void**)&p_delta, g_delta);
    cudaGetSymbolAddress((void**)&p_part,  g_part);

    __nv_bfloat16 *xa_h, *xa_l, *w1_h, *w1_l, *ya_h, *ya_l, *w2_h, *w2_l;
    cudaGetSymbolAddress((void**)&xa_h, g_xa_h);
    cudaGetSymbolAddress((void**)&xa_l, g_xa_l);
    cudaGetSymbolAddress((void**)&w1_h, g_w1_h);
    cudaGetSymbolAddress((void**)&w1_l, g_w1_l);
    cudaGetSymbolAddress((void**)&ya_h, g_ya_h);
    cudaGetSymbolAddress((void**)&ya_l, g_ya_l);
    cudaGetSymbolAddress((void**)&w2_h, g_w2_h);
    cudaGetSymbolAddress((void**)&w2_l, g_w2_l);

    constexpr int GSMEM = 2 * STAGE_BYTES;
    constexpr int SSMEM = SCAN_SMEM_FLOATS * 4;
    cudaFuncSetAttribute((const void*)gemm_mma,
                         cudaFuncAttributeMaxDynamicSharedMemorySize, GSMEM);
    cudaFuncSetAttribute((const void*)scan_k,
                         cudaFuncAttributeMaxDynamicSharedMemorySize, SSMEM);

    // #1: merged prep
    prep_k<<<10240, 256>>>(W_in, w1_h, w1_l, W_out, w2_h, w2_l, x, xa_h, xa_l);

    // #2: xz = x @ W_in
    gemm_mma<<<dim3(XZW / 64, NROWS / 128), 256, GSMEM>>>(
        xa_h, xa_l, w1_h, w1_l, p_xz, NROWS, XZW, DMODEL);

    // #3: xs = silu(conv(x_) + b)
    conv_silu_k<<<(NROWS / 4) * (DINNER / 4) / 256, 256>>>(p_xz, convw, convb, p_xs);

    // #4: bcd split-K partials   <-- profiled slot
    bcd_k<<<dim3(NROWS / 32, KSPLIT), 256>>>(p_xs, W_x, p_part);

    // #5: reduce partials -> B, C, delta
    bcd_red<<<(NROWS * 33 + 255) / 256, 256>>>(p_part, p_B, p_C, p_delta);

    // #6: selective scan
    scan_k<<<BATCH * (DINNER / 16), 256, SSMEM>>>(
        p_delta, w_dt, b_dt, p_xs, p_xz, p_B, p_C, A_log, Dp, ya_h, ya_l);

    // #7: out = yz @ W_out
    gemm_mma<<<dim3(DMODEL / 64, NROWS / 128), 256, GSMEM>>>(
        ya_h, ya_l, w2_h, w2_l, out, NROWS, DMODEL, DINNER);
}